// round 12
// baseline (speedup 1.0000x reference)
#include <cuda_runtime.h>
#include <cuda_fp16.h>
#include <cstdint>

#define NN   50000
#define EE   800000
#define C    256
#define MPAD 50048          // 391 * 128

// ---------------------------------------------------------------------------
// Scratch (__device__ globals, allocation-free rule)
// ---------------------------------------------------------------------------
__device__ __align__(16) float g_t[(size_t)NN * C];            // GEMM out (raw H, fp32)
__device__ __align__(16) __half g_ahi[(size_t)MPAD * C];
__device__ __align__(16) __half g_alo[(size_t)MPAD * C];
__device__ __align__(16) __half g_w1hi[C * C];   // B^T layout [N][K]
__device__ __align__(16) __half g_w2hi[C * C];
__device__ float g_dinv[NN];
__device__ int   g_deg[NN];
__device__ int   g_rowptr[NN + 1];
__device__ int   g_cursor[NN];
__device__ int   g_csrc[EE];

__device__ __forceinline__ uint32_t smem_u32(const void* p) {
    uint32_t a;
    asm("{ .reg .u64 t; cvta.to.shared.u64 t, %1; cvt.u32.u64 %0, t; }"
        : "=r"(a) : "l"(p));
    return a;
}

// ---------------------------------------------------------------------------
// Degree / CSR build
// ---------------------------------------------------------------------------
__global__ void deg_init(int* deg, int n) {
    int i = blockIdx.x * blockDim.x + threadIdx.x;
    if (i < n) deg[i] = 0;
}
__global__ void deg_accum(const int* __restrict__ dst, int* deg, int e) {
    int i = blockIdx.x * blockDim.x + threadIdx.x;
    if (i < e) atomicAdd(&deg[dst[i]], 1);
}
__global__ void scan_build(const int* __restrict__ deg, int* __restrict__ row_ptr,
                           int* __restrict__ cursor, float* __restrict__ dinv, int n) {
    __shared__ int part[1024];
    const int T = 1024;
    int tid = threadIdx.x;
    int chunk = (n + T - 1) / T;
    int beg = tid * chunk;
    int end = min(beg + chunk, n);
    int s = 0;
    for (int i = beg; i < end; i++) s += deg[i];
    part[tid] = s;
    __syncthreads();
    for (int off = 1; off < T; off <<= 1) {
        int v = part[tid];
        int u = (tid >= off) ? part[tid - off] : 0;
        __syncthreads();
        part[tid] = v + u;
        __syncthreads();
    }
    int run = (tid > 0) ? part[tid - 1] : 0;
    for (int i = beg; i < end; i++) {
        int c = deg[i];
        row_ptr[i] = run;
        cursor[i] = run;
        dinv[i] = rsqrtf((float)(c + 1));
        run += c;
    }
    if (tid == T - 1) row_ptr[n] = part[T - 1];
}
__global__ void csr_fill(const int* __restrict__ src, const int* __restrict__ dst,
                         int* cursor, int* __restrict__ csrc, int e) {
    int i = blockIdx.x * blockDim.x + threadIdx.x;
    if (i < e) {
        int p = atomicAdd(&cursor[dst[i]], 1);
        csrc[p] = src[i];
    }
}

// ---------------------------------------------------------------------------
// Conversion: fp32 -> (fp16 hi, fp16 lo)
// ---------------------------------------------------------------------------
union HF2 { __half2 h2; uint32_t u; };

__device__ __forceinline__ void split_f16(float v, __half& hi, __half& lo) {
    hi = __float2half_rn(v);
    lo = __float2half_rn(v - __half2float(hi));
}

__global__ void conv_x(const float* __restrict__ x, __half* __restrict__ hi,
                       __half* __restrict__ lo, int M) {
    int i = blockIdx.x * blockDim.x + threadIdx.x;      // float4 index
    if (i >= MPAD * (C / 4)) return;
    int r = i >> 6;
    float4 v = (r < M) ? __ldg((const float4*)x + i) : make_float4(0.f, 0.f, 0.f, 0.f);
    __half h0, h1, h2, h3, l0, l1, l2, l3;
    split_f16(v.x, h0, l0); split_f16(v.y, h1, l1);
    split_f16(v.z, h2, l2); split_f16(v.w, h3, l3);
    HF2 a, b; uint2 o;
    a.h2 = __halves2half2(h0, h1); b.h2 = __halves2half2(h2, h3);
    o.x = a.u; o.y = b.u;
    ((uint2*)hi)[i] = o;
    a.h2 = __halves2half2(l0, l1); b.h2 = __halves2half2(l2, l3);
    o.x = a.u; o.y = b.u;
    ((uint2*)lo)[i] = o;
}

// W [K,N] fp32 -> B^T [N][K] fp16 (hi only; A-side split carries precision)
__global__ void conv_w(const float* __restrict__ W, __half* __restrict__ hi) {
    int i = blockIdx.x * blockDim.x + threadIdx.x;      // over 256*64
    if (i >= C * (C / 4)) return;
    int n = i >> 6;
    int k4 = (i & 63) * 4;
    __half hs[4];
    #pragma unroll
    for (int j = 0; j < 4; j++)
        hs[j] = __float2half_rn(__ldg(&W[(size_t)(k4 + j) * C + n]));
    HF2 a, b; uint2 o;
    a.h2 = __halves2half2(hs[0], hs[1]); b.h2 = __halves2half2(hs[2], hs[3]);
    o.x = a.u; o.y = b.u;
    ((uint2*)hi)[i] = o;
}

// ---------------------------------------------------------------------------
// mma.sync fp16 GEMM (2-term): H = Ahi*Bh + Alo*Bh   (fp32 out)
// CTA 128x128, 8 warps of 32x64. K-chunks of 32. Bt is [N][K] ("col" operand).
// ---------------------------------------------------------------------------
#define LDS_PAD 40            // 32 + 8 pad (fp16 elems per smem row)

__device__ __forceinline__ void ldsm4(uint32_t* r, uint32_t addr) {
    asm volatile("ldmatrix.sync.aligned.m8n8.x4.shared.b16 {%0,%1,%2,%3}, [%4];"
                 : "=r"(r[0]), "=r"(r[1]), "=r"(r[2]), "=r"(r[3]) : "r"(addr));
}
__device__ __forceinline__ void mma16816(float* c, const uint32_t* a, const uint32_t* b) {
    asm volatile("mma.sync.aligned.m16n8k16.row.col.f32.f16.f16.f32 "
                 "{%0,%1,%2,%3}, {%4,%5,%6,%7}, {%8,%9}, {%0,%1,%2,%3};"
                 : "+f"(c[0]), "+f"(c[1]), "+f"(c[2]), "+f"(c[3])
                 : "r"(a[0]), "r"(a[1]), "r"(a[2]), "r"(a[3]), "r"(b[0]), "r"(b[1]));
}

__global__ __launch_bounds__(256)
void mma_gemm(const __half* __restrict__ Ahi, const __half* __restrict__ Alo,
              const __half* __restrict__ Bh,
              float* __restrict__ Hs, int Mrows) {
    __shared__ __half sAh[128][LDS_PAD];
    __shared__ __half sAl[128][LDS_PAD];
    __shared__ __half sBh[128][LDS_PAD];

    int tid = threadIdx.x, lane = tid & 31, wid = tid >> 5;
    int r0 = blockIdx.x * 128;
    int n0c = blockIdx.y * 128;          // CTA col base
    int wm = (wid & 3) * 32;             // warp row offset in tile
    int wn = (wid >> 2) * 64;            // warp col offset in tile

    int aRow = lane & 15;
    int aCol = (lane >> 4) * 8;
    int bRow = (lane & 7) + ((lane >> 4) == 1 ? 8 : 0);
    int bCol = ((lane >> 3) & 1) * 8;

    uint32_t sbAh = smem_u32(sAh), sbAl = smem_u32(sAl);
    uint32_t sbBh = smem_u32(sBh);

    // global staging map: 512 uint4 per tile, 2 per thread
    int gi0 = tid, gi1 = tid + 256;
    int gr0 = gi0 >> 2, gc0 = (gi0 & 3) * 8;
    int gr1 = gi1 >> 2, gc1 = (gi1 & 3) * 8;

    float acc[2][8][4] = {};

    #pragma unroll 1
    for (int kc = 0; kc < 8; kc++) {
        int k0 = kc * 32;
        {
            const char* pAh = (const char*)(Ahi + (size_t)(r0 + gr0) * C + k0 + gc0);
            const char* pAl = (const char*)(Alo + (size_t)(r0 + gr0) * C + k0 + gc0);
            const char* pBh = (const char*)(Bh + (size_t)(n0c + gr0) * C + k0 + gc0);
            *(uint4*)&sAh[gr0][gc0] = *(const uint4*)pAh;
            *(uint4*)&sAl[gr0][gc0] = *(const uint4*)pAl;
            *(uint4*)&sBh[gr0][gc0] = *(const uint4*)pBh;
            const char* qAh = (const char*)(Ahi + (size_t)(r0 + gr1) * C + k0 + gc1);
            const char* qAl = (const char*)(Alo + (size_t)(r0 + gr1) * C + k0 + gc1);
            const char* qBh = (const char*)(Bh + (size_t)(n0c + gr1) * C + k0 + gc1);
            *(uint4*)&sAh[gr1][gc1] = *(const uint4*)qAh;
            *(uint4*)&sAl[gr1][gc1] = *(const uint4*)qAl;
            *(uint4*)&sBh[gr1][gc1] = *(const uint4*)qBh;
        }
        __syncthreads();

        #pragma unroll
        for (int ks = 0; ks < 32; ks += 16) {
            uint32_t ah[2][4], al[2][4];
            #pragma unroll
            for (int mt = 0; mt < 2; mt++) {
                uint32_t off = (uint32_t)((wm + mt * 16 + aRow) * LDS_PAD + ks + aCol) * 2;
                ldsm4(ah[mt], sbAh + off);
                ldsm4(al[mt], sbAl + off);
            }
            #pragma unroll
            for (int nq = 0; nq < 4; nq++) {
                uint32_t bh[4];
                uint32_t off = (uint32_t)((wn + nq * 16 + bRow) * LDS_PAD + ks + bCol) * 2;
                ldsm4(bh, sbBh + off);
                #pragma unroll
                for (int sub = 0; sub < 2; sub++) {
                    int nt = nq * 2 + sub;
                    #pragma unroll
                    for (int mt = 0; mt < 2; mt++) {
                        mma16816(acc[mt][nt], ah[mt], &bh[sub * 2]);
                        mma16816(acc[mt][nt], al[mt], &bh[sub * 2]);
                    }
                }
            }
        }
        __syncthreads();
    }

    // Epilogue: write raw fp32 H
    int g = lane >> 2;
    int cq = (lane & 3) * 2;
    #pragma unroll
    for (int mt = 0; mt < 2; mt++) {
        int row0 = r0 + wm + mt * 16 + g;
        int row1 = row0 + 8;
        #pragma unroll
        for (int nt = 0; nt < 8; nt++) {
            int col = n0c + wn + nt * 8 + cq;
            if (row0 < Mrows) {
                float2 v = make_float2(acc[mt][nt][0], acc[mt][nt][1]);
                *(float2*)(Hs + (size_t)row0 * C + col) = v;
            }
            if (row1 < Mrows) {
                float2 v = make_float2(acc[mt][nt][2], acc[mt][nt][3]);
                *(float2*)(Hs + (size_t)row1 * C + col) = v;
            }
        }
    }
}

// ---------------------------------------------------------------------------
// CSR gather (R9-proven, fp32 H): out = prelu(dinv[d]*(sum dinv[s]*H[s]
//                                            + dinv[d]*H[d]) + b)
// F16OUT=1: write fp16 hi/lo splits ; F16OUT=0: write fp32
// ---------------------------------------------------------------------------
template <int F16OUT>
__global__ __launch_bounds__(256)
void gather_nodes(const float* __restrict__ Hs, float* __restrict__ outf,
                  __half* __restrict__ ohi, __half* __restrict__ olo,
                  const int* __restrict__ rowptr, const int* __restrict__ csrc,
                  const float* __restrict__ dinv, const float* __restrict__ bias,
                  const float* __restrict__ a_ptr, int n) {
    int node = blockIdx.x * (blockDim.x >> 5) + (threadIdx.x >> 5);
    if (node >= n) return;
    int lane = threadIdx.x & 31;

    float dvn = __ldg(&dinv[node]);
    const float4* self = (const float4*)(Hs + (size_t)node * C);
    float4 s0v = __ldg(&self[lane]);
    float4 s1v = __ldg(&self[lane + 32]);
    float4 accA0 = make_float4(s0v.x * dvn, s0v.y * dvn, s0v.z * dvn, s0v.w * dvn);
    float4 accA1 = make_float4(s1v.x * dvn, s1v.y * dvn, s1v.z * dvn, s1v.w * dvn);
    float4 accB0 = make_float4(0.f, 0.f, 0.f, 0.f);
    float4 accB1 = make_float4(0.f, 0.f, 0.f, 0.f);

    int beg = __ldg(&rowptr[node]);
    int end = __ldg(&rowptr[node + 1]);
    int p = beg;

    for (; p + 4 <= end; p += 4) {
        int s0 = __ldg(&csrc[p + 0]);
        int s1 = __ldg(&csrc[p + 1]);
        int s2 = __ldg(&csrc[p + 2]);
        int s3 = __ldg(&csrc[p + 3]);
        float d0 = __ldg(&dinv[s0]);
        float d1 = __ldg(&dinv[s1]);
        float d2 = __ldg(&dinv[s2]);
        float d3 = __ldg(&dinv[s3]);
        const float4* r0 = (const float4*)(Hs + (size_t)s0 * C);
        const float4* r1 = (const float4*)(Hs + (size_t)s1 * C);
        const float4* r2 = (const float4*)(Hs + (size_t)s2 * C);
        const float4* r3 = (const float4*)(Hs + (size_t)s3 * C);
        float4 v00 = __ldg(&r0[lane]);
        float4 v01 = __ldg(&r0[lane + 32]);
        float4 v10 = __ldg(&r1[lane]);
        float4 v11 = __ldg(&r1[lane + 32]);
        float4 v20 = __ldg(&r2[lane]);
        float4 v21 = __ldg(&r2[lane + 32]);
        float4 v30 = __ldg(&r3[lane]);
        float4 v31 = __ldg(&r3[lane + 32]);
        accA0.x += v00.x * d0; accA0.y += v00.y * d0; accA0.z += v00.z * d0; accA0.w += v00.w * d0;
        accA1.x += v01.x * d0; accA1.y += v01.y * d0; accA1.z += v01.z * d0; accA1.w += v01.w * d0;
        accB0.x += v10.x * d1; accB0.y += v10.y * d1; accB0.z += v10.z * d1; accB0.w += v10.w * d1;
        accB1.x += v11.x * d1; accB1.y += v11.y * d1; accB1.z += v11.z * d1; accB1.w += v11.w * d1;
        accA0.x += v20.x * d2; accA0.y += v20.y * d2; accA0.z += v20.z * d2; accA0.w += v20.w * d2;
        accA1.x += v21.x * d2; accA1.y += v21.y * d2; accA1.z += v21.z * d2; accA1.w += v21.w * d2;
        accB0.x += v30.x * d3; accB0.y += v30.y * d3; accB0.z += v30.z * d3; accB0.w += v30.w * d3;
        accB1.x += v31.x * d3; accB1.y += v31.y * d3; accB1.z += v31.z * d3; accB1.w += v31.w * d3;
    }
    for (; p < end; p++) {
        int s = __ldg(&csrc[p]);
        float ds = __ldg(&dinv[s]);
        const float4* r = (const float4*)(Hs + (size_t)s * C);
        float4 v0 = __ldg(&r[lane]);
        float4 v1 = __ldg(&r[lane + 32]);
        accA0.x += v0.x * ds; accA0.y += v0.y * ds; accA0.z += v0.z * ds; accA0.w += v0.w * ds;
        accA1.x += v1.x * ds; accA1.y += v1.y * ds; accA1.z += v1.z * ds; accA1.w += v1.w * ds;
    }

    accA0.x += accB0.x; accA0.y += accB0.y; accA0.z += accB0.z; accA0.w += accB0.w;
    accA1.x += accB1.x; accA1.y += accB1.y; accA1.z += accB1.z; accA1.w += accB1.w;

    float av = __ldg(a_ptr);
    float4 b0 = __ldg(&((const float4*)bias)[lane]);
    float4 b1 = __ldg(&((const float4*)bias)[lane + 32]);

    float o[8];
    o[0] = accA0.x * dvn + b0.x;  o[1] = accA0.y * dvn + b0.y;
    o[2] = accA0.z * dvn + b0.z;  o[3] = accA0.w * dvn + b0.w;
    o[4] = accA1.x * dvn + b1.x;  o[5] = accA1.y * dvn + b1.y;
    o[6] = accA1.z * dvn + b1.z;  o[7] = accA1.w * dvn + b1.w;
    #pragma unroll
    for (int j = 0; j < 8; j++) o[j] = o[j] >= 0.f ? o[j] : av * o[j];

    if (F16OUT) {
        __half hs[8], ls[8];
        #pragma unroll
        for (int j = 0; j < 8; j++) split_f16(o[j], hs[j], ls[j]);
        size_t base = (size_t)node * (C / 4);      // uint2 index base
        HF2 a, b; uint2 u;
        a.h2 = __halves2half2(hs[0], hs[1]); b.h2 = __halves2half2(hs[2], hs[3]);
        u.x = a.u; u.y = b.u; ((uint2*)ohi)[base + lane] = u;
        a.h2 = __halves2half2(hs[4], hs[5]); b.h2 = __halves2half2(hs[6], hs[7]);
        u.x = a.u; u.y = b.u; ((uint2*)ohi)[base + 32 + lane] = u;
        a.h2 = __halves2half2(ls[0], ls[1]); b.h2 = __halves2half2(ls[2], ls[3]);
        u.x = a.u; u.y = b.u; ((uint2*)olo)[base + lane] = u;
        a.h2 = __halves2half2(ls[4], ls[5]); b.h2 = __halves2half2(ls[6], ls[7]);
        u.x = a.u; u.y = b.u; ((uint2*)olo)[base + 32 + lane] = u;
    } else {
        float4* op = (float4*)(outf + (size_t)node * C);
        op[lane] = make_float4(o[0], o[1], o[2], o[3]);
        op[lane + 32] = make_float4(o[4], o[5], o[6], o[7]);
    }
}

// ---------------------------------------------------------------------------
// Launch: side stream hides conv_w + CSR under conv_x + GEMM1 (R9 structure).
// ---------------------------------------------------------------------------
extern "C" void kernel_launch(void* const* d_in, const int* in_sizes, int n_in,
                              void* d_out, int out_size) {
    const float* x  = (const float*)d_in[0];
    const float* W1 = (const float*)d_in[1];
    const float* b1 = (const float*)d_in[2];
    const float* W2 = (const float*)d_in[3];
    const float* b2 = (const float*)d_in[4];
    const float* a  = (const float*)d_in[5];
    const int* eidx = (const int*)d_in[6];

    const int M = in_sizes[0] / C;     // 50000
    const int E = in_sizes[6] / 2;     // 800000
    const int* src = eidx;
    const int* dst = eidx + E;

    float *tbuf, *dinv;
    int *deg, *rowptr, *cursor, *csrc;
    __half *ahi, *alo, *w1hi, *w2hi;
    cudaGetSymbolAddress((void**)&tbuf, g_t);
    cudaGetSymbolAddress((void**)&dinv, g_dinv);
    cudaGetSymbolAddress((void**)&deg, g_deg);
    cudaGetSymbolAddress((void**)&rowptr, g_rowptr);
    cudaGetSymbolAddress((void**)&cursor, g_cursor);
    cudaGetSymbolAddress((void**)&csrc, g_csrc);
    cudaGetSymbolAddress((void**)&ahi, g_ahi);
    cudaGetSymbolAddress((void**)&alo, g_alo);
    cudaGetSymbolAddress((void**)&w1hi, g_w1hi);
    cudaGetSymbolAddress((void**)&w2hi, g_w2hi);
    float* outp = (float*)d_out;

    static cudaStream_t s_side = nullptr;
    static cudaEvent_t ev_fork = nullptr, ev_w = nullptr, ev_join = nullptr;
    if (!s_side) {
        cudaStreamCreateWithFlags(&s_side, cudaStreamNonBlocking);
        cudaEventCreateWithFlags(&ev_fork, cudaEventDisableTiming);
        cudaEventCreateWithFlags(&ev_w, cudaEventDisableTiming);
        cudaEventCreateWithFlags(&ev_join, cudaEventDisableTiming);
    }

    // --- fork: conv_w + CSR build on side stream ---
    cudaEventRecord(ev_fork, 0);
    cudaStreamWaitEvent(s_side, ev_fork, 0);
    conv_w<<<(C * (C / 4) + 255) / 256, 256, 0, s_side>>>(W1, w1hi);
    conv_w<<<(C * (C / 4) + 255) / 256, 256, 0, s_side>>>(W2, w2hi);
    cudaEventRecord(ev_w, s_side);
    deg_init  <<<(M + 255) / 256, 256, 0, s_side>>>(deg, M);
    deg_accum <<<(E + 255) / 256, 256, 0, s_side>>>(dst, deg, E);
    scan_build<<<1, 1024, 0, s_side>>>(deg, rowptr, cursor, dinv, M);
    csr_fill  <<<(E + 255) / 256, 256, 0, s_side>>>(src, dst, cursor, csrc, E);
    cudaEventRecord(ev_join, s_side);

    // --- main: conv_x, then GEMM1 ---
    conv_x<<<(MPAD * (C / 4) + 255) / 256, 256>>>(x, ahi, alo, M);
    cudaStreamWaitEvent(0, ev_w, 0);
    dim3 gfull((M + 127) / 128, 2);
    const int gblocks = (M + 7) / 8;

    mma_gemm<<<gfull, 256>>>(ahi, alo, w1hi, tbuf, M);

    // join: gathers need dinv + CSR
    cudaStreamWaitEvent(0, ev_join, 0);
    gather_nodes<1><<<gblocks, 256>>>(tbuf, nullptr, ahi, alo, rowptr, csrc, dinv, b1, a, M);

    // --- layer 2 ---
    mma_gemm<<<gfull, 256>>>(ahi, alo, w2hi, tbuf, M);
    gather_nodes<0><<<gblocks, 256>>>(tbuf, outp, nullptr, nullptr, rowptr, csrc, dinv, b2, a, M);
}

// round 13
// speedup vs baseline: 1.1894x; 1.1894x over previous
#include <cuda_runtime.h>
#include <cuda_fp16.h>
#include <cstdint>

#define NN   50000
#define EE   800000
#define C    256

// ---------------------------------------------------------------------------
// Scratch (__device__ globals, allocation-free rule)
// ---------------------------------------------------------------------------
__device__ __align__(16) float g_t[(size_t)NN * C];   // GEMM out (raw H, fp32)
__device__ __align__(16) float g_h[(size_t)NN * C];   // layer-1 activations (fp32)
__device__ __align__(16) __half g_w1hi[C * C];        // B^T layout [N][K]
__device__ __align__(16) __half g_w2hi[C * C];
__device__ float g_dinv[NN];
__device__ int   g_deg[NN];
__device__ int   g_rowptr[NN + 1];
__device__ int   g_cursor[NN];
__device__ int   g_csrc[EE];

__device__ __forceinline__ uint32_t smem_u32(const void* p) {
    uint32_t a;
    asm("{ .reg .u64 t; cvta.to.shared.u64 t, %1; cvt.u32.u64 %0, t; }"
        : "=r"(a) : "l"(p));
    return a;
}

// ---------------------------------------------------------------------------
// Degree / CSR build
// ---------------------------------------------------------------------------
__global__ void deg_init(int* deg, int n) {
    int i = blockIdx.x * blockDim.x + threadIdx.x;
    if (i < n) deg[i] = 0;
}
__global__ void deg_accum(const int* __restrict__ dst, int* deg, int e) {
    int i = blockIdx.x * blockDim.x + threadIdx.x;
    if (i < e) atomicAdd(&deg[dst[i]], 1);
}
__global__ void scan_build(const int* __restrict__ deg, int* __restrict__ row_ptr,
                           int* __restrict__ cursor, float* __restrict__ dinv, int n) {
    __shared__ int part[1024];
    const int T = 1024;
    int tid = threadIdx.x;
    int chunk = (n + T - 1) / T;
    int beg = tid * chunk;
    int end = min(beg + chunk, n);
    int s = 0;
    for (int i = beg; i < end; i++) s += deg[i];
    part[tid] = s;
    __syncthreads();
    for (int off = 1; off < T; off <<= 1) {
        int v = part[tid];
        int u = (tid >= off) ? part[tid - off] : 0;
        __syncthreads();
        part[tid] = v + u;
        __syncthreads();
    }
    int run = (tid > 0) ? part[tid - 1] : 0;
    for (int i = beg; i < end; i++) {
        int c = deg[i];
        row_ptr[i] = run;
        cursor[i] = run;
        dinv[i] = rsqrtf((float)(c + 1));
        run += c;
    }
    if (tid == T - 1) row_ptr[n] = part[T - 1];
}
__global__ void csr_fill(const int* __restrict__ src, const int* __restrict__ dst,
                         int* cursor, int* __restrict__ csrc, int e) {
    int i = blockIdx.x * blockDim.x + threadIdx.x;
    if (i < e) {
        int p = atomicAdd(&cursor[dst[i]], 1);
        csrc[p] = src[i];
    }
}

// ---------------------------------------------------------------------------
// W [K,N] fp32 -> B^T [N][K] fp16 (A-side split carries the precision)
// ---------------------------------------------------------------------------
union HF2 { __half2 h2; uint32_t u; };

__global__ void conv_w(const float* __restrict__ W, __half* __restrict__ hi) {
    int i = blockIdx.x * blockDim.x + threadIdx.x;      // over 256*64
    if (i >= C * (C / 4)) return;
    int n = i >> 6;
    int k4 = (i & 63) * 4;
    __half hs[4];
    #pragma unroll
    for (int j = 0; j < 4; j++)
        hs[j] = __float2half_rn(__ldg(&W[(size_t)(k4 + j) * C + n]));
    HF2 a, b; uint2 o;
    a.h2 = __halves2half2(hs[0], hs[1]); b.h2 = __halves2half2(hs[2], hs[3]);
    o.x = a.u; o.y = b.u;
    ((uint2*)hi)[i] = o;
}

// ---------------------------------------------------------------------------
// mma.sync fp16 GEMM, 2-term, fp32 A with in-staging split:
//   H = f16(A)*Bh + f16(A - f16(A))*Bh
// CTA 128x128, 8 warps of 32x64, K-chunks of 32. Bt is [N][K] ("col").
// ---------------------------------------------------------------------------
#define LDS_PAD 40            // fp16 elems per smem row (conflict-free ldsm)

__device__ __forceinline__ void ldsm4(uint32_t* r, uint32_t addr) {
    asm volatile("ldmatrix.sync.aligned.m8n8.x4.shared.b16 {%0,%1,%2,%3}, [%4];"
                 : "=r"(r[0]), "=r"(r[1]), "=r"(r[2]), "=r"(r[3]) : "r"(addr));
}
__device__ __forceinline__ void mma16816(float* c, const uint32_t* a, const uint32_t* b) {
    asm volatile("mma.sync.aligned.m16n8k16.row.col.f32.f16.f16.f32 "
                 "{%0,%1,%2,%3}, {%4,%5,%6,%7}, {%8,%9}, {%0,%1,%2,%3};"
                 : "+f"(c[0]), "+f"(c[1]), "+f"(c[2]), "+f"(c[3])
                 : "r"(a[0]), "r"(a[1]), "r"(a[2]), "r"(a[3]), "r"(b[0]), "r"(b[1]));
}

__global__ __launch_bounds__(256)
void mma_gemm(const float* __restrict__ A, const __half* __restrict__ Bh,
              float* __restrict__ Hs, int Mrows) {
    __shared__ __half sAh[128][LDS_PAD];
    __shared__ __half sAl[128][LDS_PAD];
    __shared__ __half sBh[128][LDS_PAD];

    int tid = threadIdx.x, lane = tid & 31, wid = tid >> 5;
    int r0 = blockIdx.x * 128;
    int n0c = blockIdx.y * 128;
    int wm = (wid & 3) * 32;
    int wn = (wid >> 2) * 64;

    int aRow = lane & 15;
    int aCol = (lane >> 4) * 8;
    int bRow = (lane & 7) + ((lane >> 4) == 1 ? 8 : 0);
    int bCol = ((lane >> 3) & 1) * 8;

    uint32_t sbAh = smem_u32(sAh), sbAl = smem_u32(sAl);
    uint32_t sbBh = smem_u32(sBh);

    // A staging: 128 rows x 32 fp32 = 1024 uint4 -> 4 per thread
    // B staging: 128 rows x 32 fp16 = 512 uint4  -> 2 per thread
    float acc[2][8][4] = {};

    #pragma unroll 1
    for (int kc = 0; kc < 8; kc++) {
        int k0 = kc * 32;
        // stage A with inline fp16 split
        #pragma unroll
        for (int t = 0; t < 4; t++) {
            int idx = tid + t * 256;
            int row = idx >> 3;
            int c4 = (idx & 7) * 4;
            int gr = r0 + row;
            float4 v = (gr < Mrows)
                ? *(const float4*)(A + (size_t)gr * C + k0 + c4)
                : make_float4(0.f, 0.f, 0.f, 0.f);
            __half h0 = __float2half_rn(v.x), h1 = __float2half_rn(v.y);
            __half h2 = __float2half_rn(v.z), h3 = __float2half_rn(v.w);
            __half l0 = __float2half_rn(v.x - __half2float(h0));
            __half l1 = __float2half_rn(v.y - __half2float(h1));
            __half l2 = __float2half_rn(v.z - __half2float(h2));
            __half l3 = __float2half_rn(v.w - __half2float(h3));
            HF2 p0, p1; uint2 u;
            p0.h2 = __halves2half2(h0, h1); p1.h2 = __halves2half2(h2, h3);
            u.x = p0.u; u.y = p1.u;
            *(uint2*)&sAh[row][c4] = u;
            p0.h2 = __halves2half2(l0, l1); p1.h2 = __halves2half2(l2, l3);
            u.x = p0.u; u.y = p1.u;
            *(uint2*)&sAl[row][c4] = u;
        }
        // stage B
        #pragma unroll
        for (int t = 0; t < 2; t++) {
            int idx = tid + t * 256;
            int row = idx >> 2;
            int c8 = (idx & 3) * 8;
            *(uint4*)&sBh[row][c8] =
                *(const uint4*)(Bh + (size_t)(n0c + row) * C + k0 + c8);
        }
        __syncthreads();

        #pragma unroll
        for (int ks = 0; ks < 32; ks += 16) {
            uint32_t ah[2][4], al[2][4];
            #pragma unroll
            for (int mt = 0; mt < 2; mt++) {
                uint32_t off = (uint32_t)((wm + mt * 16 + aRow) * LDS_PAD + ks + aCol) * 2;
                ldsm4(ah[mt], sbAh + off);
                ldsm4(al[mt], sbAl + off);
            }
            #pragma unroll
            for (int nq = 0; nq < 4; nq++) {
                uint32_t bh[4];
                uint32_t off = (uint32_t)((wn + nq * 16 + bRow) * LDS_PAD + ks + bCol) * 2;
                ldsm4(bh, sbBh + off);
                #pragma unroll
                for (int sub = 0; sub < 2; sub++) {
                    int nt = nq * 2 + sub;
                    #pragma unroll
                    for (int mt = 0; mt < 2; mt++) {
                        mma16816(acc[mt][nt], ah[mt], &bh[sub * 2]);
                        mma16816(acc[mt][nt], al[mt], &bh[sub * 2]);
                    }
                }
            }
        }
        __syncthreads();
    }

    // Epilogue: write raw fp32 H
    int g = lane >> 2;
    int cq = (lane & 3) * 2;
    #pragma unroll
    for (int mt = 0; mt < 2; mt++) {
        int row0 = r0 + wm + mt * 16 + g;
        int row1 = row0 + 8;
        #pragma unroll
        for (int nt = 0; nt < 8; nt++) {
            int col = n0c + wn + nt * 8 + cq;
            if (row0 < Mrows) {
                float2 v = make_float2(acc[mt][nt][0], acc[mt][nt][1]);
                *(float2*)(Hs + (size_t)row0 * C + col) = v;
            }
            if (row1 < Mrows) {
                float2 v = make_float2(acc[mt][nt][2], acc[mt][nt][3]);
                *(float2*)(Hs + (size_t)row1 * C + col) = v;
            }
        }
    }
}

// ---------------------------------------------------------------------------
// CSR gather (R9-proven, fp32 in/out):
// out[d] = prelu(dinv[d]*(sum_e dinv[s_e]*H[s_e] + dinv[d]*H[d]) + b)
// ---------------------------------------------------------------------------
__global__ __launch_bounds__(256)
void gather_nodes(const float* __restrict__ Hs, float* __restrict__ outf,
                  const int* __restrict__ rowptr, const int* __restrict__ csrc,
                  const float* __restrict__ dinv, const float* __restrict__ bias,
                  const float* __restrict__ a_ptr, int n) {
    int node = blockIdx.x * (blockDim.x >> 5) + (threadIdx.x >> 5);
    if (node >= n) return;
    int lane = threadIdx.x & 31;

    float dvn = __ldg(&dinv[node]);
    const float4* self = (const float4*)(Hs + (size_t)node * C);
    float4 s0v = __ldg(&self[lane]);
    float4 s1v = __ldg(&self[lane + 32]);
    float4 accA0 = make_float4(s0v.x * dvn, s0v.y * dvn, s0v.z * dvn, s0v.w * dvn);
    float4 accA1 = make_float4(s1v.x * dvn, s1v.y * dvn, s1v.z * dvn, s1v.w * dvn);
    float4 accB0 = make_float4(0.f, 0.f, 0.f, 0.f);
    float4 accB1 = make_float4(0.f, 0.f, 0.f, 0.f);

    int beg = __ldg(&rowptr[node]);
    int end = __ldg(&rowptr[node + 1]);
    int p = beg;

    for (; p + 4 <= end; p += 4) {
        int s0 = __ldg(&csrc[p + 0]);
        int s1 = __ldg(&csrc[p + 1]);
        int s2 = __ldg(&csrc[p + 2]);
        int s3 = __ldg(&csrc[p + 3]);
        float d0 = __ldg(&dinv[s0]);
        float d1 = __ldg(&dinv[s1]);
        float d2 = __ldg(&dinv[s2]);
        float d3 = __ldg(&dinv[s3]);
        const float4* r0 = (const float4*)(Hs + (size_t)s0 * C);
        const float4* r1 = (const float4*)(Hs + (size_t)s1 * C);
        const float4* r2 = (const float4*)(Hs + (size_t)s2 * C);
        const float4* r3 = (const float4*)(Hs + (size_t)s3 * C);
        float4 v00 = __ldg(&r0[lane]);
        float4 v01 = __ldg(&r0[lane + 32]);
        float4 v10 = __ldg(&r1[lane]);
        float4 v11 = __ldg(&r1[lane + 32]);
        float4 v20 = __ldg(&r2[lane]);
        float4 v21 = __ldg(&r2[lane + 32]);
        float4 v30 = __ldg(&r3[lane]);
        float4 v31 = __ldg(&r3[lane + 32]);
        accA0.x += v00.x * d0; accA0.y += v00.y * d0; accA0.z += v00.z * d0; accA0.w += v00.w * d0;
        accA1.x += v01.x * d0; accA1.y += v01.y * d0; accA1.z += v01.z * d0; accA1.w += v01.w * d0;
        accB0.x += v10.x * d1; accB0.y += v10.y * d1; accB0.z += v10.z * d1; accB0.w += v10.w * d1;
        accB1.x += v11.x * d1; accB1.y += v11.y * d1; accB1.z += v11.z * d1; accB1.w += v11.w * d1;
        accA0.x += v20.x * d2; accA0.y += v20.y * d2; accA0.z += v20.z * d2; accA0.w += v20.w * d2;
        accA1.x += v21.x * d2; accA1.y += v21.y * d2; accA1.z += v21.z * d2; accA1.w += v21.w * d2;
        accB0.x += v30.x * d3; accB0.y += v30.y * d3; accB0.z += v30.z * d3; accB0.w += v30.w * d3;
        accB1.x += v31.x * d3; accB1.y += v31.y * d3; accB1.z += v31.z * d3; accB1.w += v31.w * d3;
    }
    for (; p < end; p++) {
        int s = __ldg(&csrc[p]);
        float ds = __ldg(&dinv[s]);
        const float4* r = (const float4*)(Hs + (size_t)s * C);
        float4 v0 = __ldg(&r[lane]);
        float4 v1 = __ldg(&r[lane + 32]);
        accA0.x += v0.x * ds; accA0.y += v0.y * ds; accA0.z += v0.z * ds; accA0.w += v0.w * ds;
        accA1.x += v1.x * ds; accA1.y += v1.y * ds; accA1.z += v1.z * ds; accA1.w += v1.w * ds;
    }

    accA0.x += accB0.x; accA0.y += accB0.y; accA0.z += accB0.z; accA0.w += accB0.w;
    accA1.x += accB1.x; accA1.y += accB1.y; accA1.z += accB1.z; accA1.w += accB1.w;

    float av = __ldg(a_ptr);
    float4 b0 = __ldg(&((const float4*)bias)[lane]);
    float4 b1 = __ldg(&((const float4*)bias)[lane + 32]);

    float o[8];
    o[0] = accA0.x * dvn + b0.x;  o[1] = accA0.y * dvn + b0.y;
    o[2] = accA0.z * dvn + b0.z;  o[3] = accA0.w * dvn + b0.w;
    o[4] = accA1.x * dvn + b1.x;  o[5] = accA1.y * dvn + b1.y;
    o[6] = accA1.z * dvn + b1.z;  o[7] = accA1.w * dvn + b1.w;
    #pragma unroll
    for (int j = 0; j < 8; j++) o[j] = o[j] >= 0.f ? o[j] : av * o[j];

    float4* op = (float4*)(outf + (size_t)node * C);
    op[lane] = make_float4(o[0], o[1], o[2], o[3]);
    op[lane + 32] = make_float4(o[4], o[5], o[6], o[7]);
}

// ---------------------------------------------------------------------------
// Launch: side stream hides conv_w + CSR under GEMM1 (R9 structure, no conv_x)
// ---------------------------------------------------------------------------
extern "C" void kernel_launch(void* const* d_in, const int* in_sizes, int n_in,
                              void* d_out, int out_size) {
    const float* x  = (const float*)d_in[0];
    const float* W1 = (const float*)d_in[1];
    const float* b1 = (const float*)d_in[2];
    const float* W2 = (const float*)d_in[3];
    const float* b2 = (const float*)d_in[4];
    const float* a  = (const float*)d_in[5];
    const int* eidx = (const int*)d_in[6];

    const int M = in_sizes[0] / C;     // 50000
    const int E = in_sizes[6] / 2;     // 800000
    const int* src = eidx;
    const int* dst = eidx + E;

    float *tbuf, *hbuf, *dinv;
    int *deg, *rowptr, *cursor, *csrc;
    __half *w1hi, *w2hi;
    cudaGetSymbolAddress((void**)&tbuf, g_t);
    cudaGetSymbolAddress((void**)&hbuf, g_h);
    cudaGetSymbolAddress((void**)&dinv, g_dinv);
    cudaGetSymbolAddress((void**)&deg, g_deg);
    cudaGetSymbolAddress((void**)&rowptr, g_rowptr);
    cudaGetSymbolAddress((void**)&cursor, g_cursor);
    cudaGetSymbolAddress((void**)&csrc, g_csrc);
    cudaGetSymbolAddress((void**)&w1hi, g_w1hi);
    cudaGetSymbolAddress((void**)&w2hi, g_w2hi);
    float* outp = (float*)d_out;

    static cudaStream_t s_side = nullptr;
    static cudaEvent_t ev_fork = nullptr, ev_w = nullptr, ev_join = nullptr;
    if (!s_side) {
        cudaStreamCreateWithFlags(&s_side, cudaStreamNonBlocking);
        cudaEventCreateWithFlags(&ev_fork, cudaEventDisableTiming);
        cudaEventCreateWithFlags(&ev_w, cudaEventDisableTiming);
        cudaEventCreateWithFlags(&ev_join, cudaEventDisableTiming);
    }

    // --- fork: conv_w + CSR build on side stream ---
    cudaEventRecord(ev_fork, 0);
    cudaStreamWaitEvent(s_side, ev_fork, 0);
    conv_w<<<(C * (C / 4) + 255) / 256, 256, 0, s_side>>>(W1, w1hi);
    conv_w<<<(C * (C / 4) + 255) / 256, 256, 0, s_side>>>(W2, w2hi);
    cudaEventRecord(ev_w, s_side);
    deg_init  <<<(M + 255) / 256, 256, 0, s_side>>>(deg, M);
    deg_accum <<<(E + 255) / 256, 256, 0, s_side>>>(dst, deg, E);
    scan_build<<<1, 1024, 0, s_side>>>(deg, rowptr, cursor, dinv, M);
    csr_fill  <<<(E + 255) / 256, 256, 0, s_side>>>(src, dst, cursor, csrc, E);
    cudaEventRecord(ev_join, s_side);

    dim3 gfull((M + 127) / 128, 2);
    const int gblocks = (M + 7) / 8;

    // --- main: GEMM1 on raw fp32 x (in-staging split; needs only W1) ---
    cudaStreamWaitEvent(0, ev_w, 0);
    mma_gemm<<<gfull, 256>>>(x, w1hi, tbuf, M);

    // join: gathers need dinv + CSR
    cudaStreamWaitEvent(0, ev_join, 0);
    gather_nodes<<<gblocks, 256>>>(tbuf, hbuf, rowptr, csrc, dinv, b1, a, M);

    // --- layer 2 ---
    mma_gemm<<<gfull, 256>>>(hbuf, w2hi, tbuf, M);
    gather_nodes<<<gblocks, 256>>>(tbuf, outp, rowptr, csrc, dinv, b2, a, M);
}

// round 14
// speedup vs baseline: 1.2533x; 1.0537x over previous
#include <cuda_runtime.h>
#include <cuda_fp16.h>
#include <cstdint>

#define NN   50000
#define EE   800000
#define C    256

// ---------------------------------------------------------------------------
// Scratch (__device__ globals, allocation-free rule)
// ---------------------------------------------------------------------------
__device__ __align__(16) float  g_t[(size_t)NN * C];   // GEMM out (raw H, fp32)
__device__ __align__(16) __half g_h[(size_t)NN * C];   // layer-1 activations (fp16)
__device__ __align__(16) __half g_w1hi[C * C];         // B^T layout [N][K]
__device__ __align__(16) __half g_w2hi[C * C];
__device__ float g_dinv[NN];
__device__ int   g_deg[NN];
__device__ int   g_rowptr[NN + 1];
__device__ int   g_cursor[NN];
__device__ int   g_csrc[EE];

__device__ __forceinline__ uint32_t smem_u32(const void* p) {
    uint32_t a;
    asm("{ .reg .u64 t; cvta.to.shared.u64 t, %1; cvt.u32.u64 %0, t; }"
        : "=r"(a) : "l"(p));
    return a;
}

// ---------------------------------------------------------------------------
// Degree / CSR build
// ---------------------------------------------------------------------------
__global__ void deg_init(int* deg, int n) {
    int i = blockIdx.x * blockDim.x + threadIdx.x;
    if (i < n) deg[i] = 0;
}
__global__ void deg_accum(const int* __restrict__ dst, int* deg, int e) {
    int i = blockIdx.x * blockDim.x + threadIdx.x;
    if (i < e) atomicAdd(&deg[dst[i]], 1);
}
__global__ void scan_build(const int* __restrict__ deg, int* __restrict__ row_ptr,
                           int* __restrict__ cursor, float* __restrict__ dinv, int n) {
    __shared__ int part[1024];
    const int T = 1024;
    int tid = threadIdx.x;
    int chunk = (n + T - 1) / T;
    int beg = tid * chunk;
    int end = min(beg + chunk, n);
    int s = 0;
    for (int i = beg; i < end; i++) s += deg[i];
    part[tid] = s;
    __syncthreads();
    for (int off = 1; off < T; off <<= 1) {
        int v = part[tid];
        int u = (tid >= off) ? part[tid - off] : 0;
        __syncthreads();
        part[tid] = v + u;
        __syncthreads();
    }
    int run = (tid > 0) ? part[tid - 1] : 0;
    for (int i = beg; i < end; i++) {
        int c = deg[i];
        row_ptr[i] = run;
        cursor[i] = run;
        dinv[i] = rsqrtf((float)(c + 1));
        run += c;
    }
    if (tid == T - 1) row_ptr[n] = part[T - 1];
}
__global__ void csr_fill(const int* __restrict__ src, const int* __restrict__ dst,
                         int* cursor, int* __restrict__ csrc, int e) {
    int i = blockIdx.x * blockDim.x + threadIdx.x;
    if (i < e) {
        int p = atomicAdd(&cursor[dst[i]], 1);
        csrc[p] = src[i];
    }
}

// ---------------------------------------------------------------------------
// W [K,N] fp32 -> B^T [N][K] fp16 (A-side split carries the precision)
// ---------------------------------------------------------------------------
union HF2 { __half2 h2; uint32_t u; };

__global__ void conv_w(const float* __restrict__ W, __half* __restrict__ hi) {
    int i = blockIdx.x * blockDim.x + threadIdx.x;      // over 256*64
    if (i >= C * (C / 4)) return;
    int n = i >> 6;
    int k4 = (i & 63) * 4;
    __half hs[4];
    #pragma unroll
    for (int j = 0; j < 4; j++)
        hs[j] = __float2half_rn(__ldg(&W[(size_t)(k4 + j) * C + n]));
    HF2 a, b; uint2 o;
    a.h2 = __halves2half2(hs[0], hs[1]); b.h2 = __halves2half2(hs[2], hs[3]);
    o.x = a.u; o.y = b.u;
    ((uint2*)hi)[i] = o;
}

// ---------------------------------------------------------------------------
// Shared MMA helpers
// ---------------------------------------------------------------------------
#define LDS_PAD 40            // fp16 elems per smem row (conflict-free ldsm)

__device__ __forceinline__ void ldsm4(uint32_t* r, uint32_t addr) {
    asm volatile("ldmatrix.sync.aligned.m8n8.x4.shared.b16 {%0,%1,%2,%3}, [%4];"
                 : "=r"(r[0]), "=r"(r[1]), "=r"(r[2]), "=r"(r[3]) : "r"(addr));
}
__device__ __forceinline__ void mma16816(float* c, const uint32_t* a, const uint32_t* b) {
    asm volatile("mma.sync.aligned.m16n8k16.row.col.f32.f16.f16.f32 "
                 "{%0,%1,%2,%3}, {%4,%5,%6,%7}, {%8,%9}, {%0,%1,%2,%3};"
                 : "+f"(c[0]), "+f"(c[1]), "+f"(c[2]), "+f"(c[3])
                 : "r"(a[0]), "r"(a[1]), "r"(a[2]), "r"(a[3]), "r"(b[0]), "r"(b[1]));
}

// ---------------------------------------------------------------------------
// GEMM1: fp32 A, in-staging fp16 split, 2-term (R13-proven):
//   H = f16(A)*Bh + f16(A - f16(A))*Bh
// ---------------------------------------------------------------------------
__global__ __launch_bounds__(256)
void mma_gemm(const float* __restrict__ A, const __half* __restrict__ Bh,
              float* __restrict__ Hs, int Mrows) {
    __shared__ __half sAh[128][LDS_PAD];
    __shared__ __half sAl[128][LDS_PAD];
    __shared__ __half sBh[128][LDS_PAD];

    int tid = threadIdx.x, lane = tid & 31, wid = tid >> 5;
    int r0 = blockIdx.x * 128;
    int n0c = blockIdx.y * 128;
    int wm = (wid & 3) * 32;
    int wn = (wid >> 2) * 64;

    int aRow = lane & 15;
    int aCol = (lane >> 4) * 8;
    int bRow = (lane & 7) + ((lane >> 4) == 1 ? 8 : 0);
    int bCol = ((lane >> 3) & 1) * 8;

    uint32_t sbAh = smem_u32(sAh), sbAl = smem_u32(sAl);
    uint32_t sbBh = smem_u32(sBh);

    float acc[2][8][4] = {};

    #pragma unroll 1
    for (int kc = 0; kc < 8; kc++) {
        int k0 = kc * 32;
        #pragma unroll
        for (int t = 0; t < 4; t++) {
            int idx = tid + t * 256;
            int row = idx >> 3;
            int c4 = (idx & 7) * 4;
            int gr = r0 + row;
            float4 v = (gr < Mrows)
                ? *(const float4*)(A + (size_t)gr * C + k0 + c4)
                : make_float4(0.f, 0.f, 0.f, 0.f);
            __half h0 = __float2half_rn(v.x), h1 = __float2half_rn(v.y);
            __half h2 = __float2half_rn(v.z), h3 = __float2half_rn(v.w);
            __half l0 = __float2half_rn(v.x - __half2float(h0));
            __half l1 = __float2half_rn(v.y - __half2float(h1));
            __half l2 = __float2half_rn(v.z - __half2float(h2));
            __half l3 = __float2half_rn(v.w - __half2float(h3));
            HF2 p0, p1; uint2 u;
            p0.h2 = __halves2half2(h0, h1); p1.h2 = __halves2half2(h2, h3);
            u.x = p0.u; u.y = p1.u;
            *(uint2*)&sAh[row][c4] = u;
            p0.h2 = __halves2half2(l0, l1); p1.h2 = __halves2half2(l2, l3);
            u.x = p0.u; u.y = p1.u;
            *(uint2*)&sAl[row][c4] = u;
        }
        #pragma unroll
        for (int t = 0; t < 2; t++) {
            int idx = tid + t * 256;
            int row = idx >> 2;
            int c8 = (idx & 3) * 8;
            *(uint4*)&sBh[row][c8] =
                *(const uint4*)(Bh + (size_t)(n0c + row) * C + k0 + c8);
        }
        __syncthreads();

        #pragma unroll
        for (int ks = 0; ks < 32; ks += 16) {
            uint32_t ah[2][4], al[2][4];
            #pragma unroll
            for (int mt = 0; mt < 2; mt++) {
                uint32_t off = (uint32_t)((wm + mt * 16 + aRow) * LDS_PAD + ks + aCol) * 2;
                ldsm4(ah[mt], sbAh + off);
                ldsm4(al[mt], sbAl + off);
            }
            #pragma unroll
            for (int nq = 0; nq < 4; nq++) {
                uint32_t bh[4];
                uint32_t off = (uint32_t)((wn + nq * 16 + bRow) * LDS_PAD + ks + bCol) * 2;
                ldsm4(bh, sbBh + off);
                #pragma unroll
                for (int sub = 0; sub < 2; sub++) {
                    int nt = nq * 2 + sub;
                    #pragma unroll
                    for (int mt = 0; mt < 2; mt++) {
                        mma16816(acc[mt][nt], ah[mt], &bh[sub * 2]);
                        mma16816(acc[mt][nt], al[mt], &bh[sub * 2]);
                    }
                }
            }
        }
        __syncthreads();
    }

    int g = lane >> 2;
    int cq = (lane & 3) * 2;
    #pragma unroll
    for (int mt = 0; mt < 2; mt++) {
        int row0 = r0 + wm + mt * 16 + g;
        int row1 = row0 + 8;
        #pragma unroll
        for (int nt = 0; nt < 8; nt++) {
            int col = n0c + wn + nt * 8 + cq;
            if (row0 < Mrows) {
                float2 v = make_float2(acc[mt][nt][0], acc[mt][nt][1]);
                *(float2*)(Hs + (size_t)row0 * C + col) = v;
            }
            if (row1 < Mrows) {
                float2 v = make_float2(acc[mt][nt][2], acc[mt][nt][3]);
                *(float2*)(Hs + (size_t)row1 * C + col) = v;
            }
        }
    }
}

// ---------------------------------------------------------------------------
// GEMM2: fp16 A (exact), single-term: H = A*Bh. Half the MMAs of GEMM1.
// ---------------------------------------------------------------------------
__global__ __launch_bounds__(256)
void mma_gemm_f16(const __half* __restrict__ A, const __half* __restrict__ Bh,
                  float* __restrict__ Hs, int Mrows) {
    __shared__ __half sAh[128][LDS_PAD];
    __shared__ __half sBh[128][LDS_PAD];

    int tid = threadIdx.x, lane = tid & 31, wid = tid >> 5;
    int r0 = blockIdx.x * 128;
    int n0c = blockIdx.y * 128;
    int wm = (wid & 3) * 32;
    int wn = (wid >> 2) * 64;

    int aRow = lane & 15;
    int aCol = (lane >> 4) * 8;
    int bRow = (lane & 7) + ((lane >> 4) == 1 ? 8 : 0);
    int bCol = ((lane >> 3) & 1) * 8;

    uint32_t sbAh = smem_u32(sAh);
    uint32_t sbBh = smem_u32(sBh);

    float acc[2][8][4] = {};

    #pragma unroll 1
    for (int kc = 0; kc < 8; kc++) {
        int k0 = kc * 32;
        // stage A (fp16 direct): 128 rows x 32 halfs = 512 uint4, 2/thread
        #pragma unroll
        for (int t = 0; t < 2; t++) {
            int idx = tid + t * 256;
            int row = idx >> 2;
            int c8 = (idx & 3) * 8;
            int gr = r0 + row;
            uint4 v = (gr < Mrows)
                ? *(const uint4*)(A + (size_t)gr * C + k0 + c8)
                : make_uint4(0u, 0u, 0u, 0u);
            *(uint4*)&sAh[row][c8] = v;
        }
        // stage B
        #pragma unroll
        for (int t = 0; t < 2; t++) {
            int idx = tid + t * 256;
            int row = idx >> 2;
            int c8 = (idx & 3) * 8;
            *(uint4*)&sBh[row][c8] =
                *(const uint4*)(Bh + (size_t)(n0c + row) * C + k0 + c8);
        }
        __syncthreads();

        #pragma unroll
        for (int ks = 0; ks < 32; ks += 16) {
            uint32_t ah[2][4];
            #pragma unroll
            for (int mt = 0; mt < 2; mt++) {
                uint32_t off = (uint32_t)((wm + mt * 16 + aRow) * LDS_PAD + ks + aCol) * 2;
                ldsm4(ah[mt], sbAh + off);
            }
            #pragma unroll
            for (int nq = 0; nq < 4; nq++) {
                uint32_t bh[4];
                uint32_t off = (uint32_t)((wn + nq * 16 + bRow) * LDS_PAD + ks + bCol) * 2;
                ldsm4(bh, sbBh + off);
                #pragma unroll
                for (int sub = 0; sub < 2; sub++) {
                    int nt = nq * 2 + sub;
                    #pragma unroll
                    for (int mt = 0; mt < 2; mt++)
                        mma16816(acc[mt][nt], ah[mt], &bh[sub * 2]);
                }
            }
        }
        __syncthreads();
    }

    int g = lane >> 2;
    int cq = (lane & 3) * 2;
    #pragma unroll
    for (int mt = 0; mt < 2; mt++) {
        int row0 = r0 + wm + mt * 16 + g;
        int row1 = row0 + 8;
        #pragma unroll
        for (int nt = 0; nt < 8; nt++) {
            int col = n0c + wn + nt * 8 + cq;
            if (row0 < Mrows) {
                float2 v = make_float2(acc[mt][nt][0], acc[mt][nt][1]);
                *(float2*)(Hs + (size_t)row0 * C + col) = v;
            }
            if (row1 < Mrows) {
                float2 v = make_float2(acc[mt][nt][2], acc[mt][nt][3]);
                *(float2*)(Hs + (size_t)row1 * C + col) = v;
            }
        }
    }
}

// ---------------------------------------------------------------------------
// CSR gather (R9/R13-proven core):
// out[d] = prelu(dinv[d]*(sum_e dinv[s_e]*H[s_e] + dinv[d]*H[d]) + b)
// F16OUT=1: write fp16 h (layer-2 input) ; F16OUT=0: write fp32 d_out
// ---------------------------------------------------------------------------
template <int F16OUT>
__global__ __launch_bounds__(256)
void gather_nodes(const float* __restrict__ Hs, float* __restrict__ outf,
                  __half* __restrict__ outh,
                  const int* __restrict__ rowptr, const int* __restrict__ csrc,
                  const float* __restrict__ dinv, const float* __restrict__ bias,
                  const float* __restrict__ a_ptr, int n) {
    int node = blockIdx.x * (blockDim.x >> 5) + (threadIdx.x >> 5);
    if (node >= n) return;
    int lane = threadIdx.x & 31;

    float dvn = __ldg(&dinv[node]);
    const float4* self = (const float4*)(Hs + (size_t)node * C);
    float4 s0v = __ldg(&self[lane]);
    float4 s1v = __ldg(&self[lane + 32]);
    float4 accA0 = make_float4(s0v.x * dvn, s0v.y * dvn, s0v.z * dvn, s0v.w * dvn);
    float4 accA1 = make_float4(s1v.x * dvn, s1v.y * dvn, s1v.z * dvn, s1v.w * dvn);
    float4 accB0 = make_float4(0.f, 0.f, 0.f, 0.f);
    float4 accB1 = make_float4(0.f, 0.f, 0.f, 0.f);

    int beg = __ldg(&rowptr[node]);
    int end = __ldg(&rowptr[node + 1]);
    int p = beg;

    for (; p + 4 <= end; p += 4) {
        int s0 = __ldg(&csrc[p + 0]);
        int s1 = __ldg(&csrc[p + 1]);
        int s2 = __ldg(&csrc[p + 2]);
        int s3 = __ldg(&csrc[p + 3]);
        float d0 = __ldg(&dinv[s0]);
        float d1 = __ldg(&dinv[s1]);
        float d2 = __ldg(&dinv[s2]);
        float d3 = __ldg(&dinv[s3]);
        const float4* r0 = (const float4*)(Hs + (size_t)s0 * C);
        const float4* r1 = (const float4*)(Hs + (size_t)s1 * C);
        const float4* r2 = (const float4*)(Hs + (size_t)s2 * C);
        const float4* r3 = (const float4*)(Hs + (size_t)s3 * C);
        float4 v00 = __ldg(&r0[lane]);
        float4 v01 = __ldg(&r0[lane + 32]);
        float4 v10 = __ldg(&r1[lane]);
        float4 v11 = __ldg(&r1[lane + 32]);
        float4 v20 = __ldg(&r2[lane]);
        float4 v21 = __ldg(&r2[lane + 32]);
        float4 v30 = __ldg(&r3[lane]);
        float4 v31 = __ldg(&r3[lane + 32]);
        accA0.x += v00.x * d0; accA0.y += v00.y * d0; accA0.z += v00.z * d0; accA0.w += v00.w * d0;
        accA1.x += v01.x * d0; accA1.y += v01.y * d0; accA1.z += v01.z * d0; accA1.w += v01.w * d0;
        accB0.x += v10.x * d1; accB0.y += v10.y * d1; accB0.z += v10.z * d1; accB0.w += v10.w * d1;
        accB1.x += v11.x * d1; accB1.y += v11.y * d1; accB1.z += v11.z * d1; accB1.w += v11.w * d1;
        accA0.x += v20.x * d2; accA0.y += v20.y * d2; accA0.z += v20.z * d2; accA0.w += v20.w * d2;
        accA1.x += v21.x * d2; accA1.y += v21.y * d2; accA1.z += v21.z * d2; accA1.w += v21.w * d2;
        accB0.x += v30.x * d3; accB0.y += v30.y * d3; accB0.z += v30.z * d3; accB0.w += v30.w * d3;
        accB1.x += v31.x * d3; accB1.y += v31.y * d3; accB1.z += v31.z * d3; accB1.w += v31.w * d3;
    }
    for (; p < end; p++) {
        int s = __ldg(&csrc[p]);
        float ds = __ldg(&dinv[s]);
        const float4* r = (const float4*)(Hs + (size_t)s * C);
        float4 v0 = __ldg(&r[lane]);
        float4 v1 = __ldg(&r[lane + 32]);
        accA0.x += v0.x * ds; accA0.y += v0.y * ds; accA0.z += v0.z * ds; accA0.w += v0.w * ds;
        accA1.x += v1.x * ds; accA1.y += v1.y * ds; accA1.z += v1.z * ds; accA1.w += v1.w * ds;
    }

    accA0.x += accB0.x; accA0.y += accB0.y; accA0.z += accB0.z; accA0.w += accB0.w;
    accA1.x += accB1.x; accA1.y += accB1.y; accA1.z += accB1.z; accA1.w += accB1.w;

    float av = __ldg(a_ptr);
    float4 b0 = __ldg(&((const float4*)bias)[lane]);
    float4 b1 = __ldg(&((const float4*)bias)[lane + 32]);

    float o[8];
    o[0] = accA0.x * dvn + b0.x;  o[1] = accA0.y * dvn + b0.y;
    o[2] = accA0.z * dvn + b0.z;  o[3] = accA0.w * dvn + b0.w;
    o[4] = accA1.x * dvn + b1.x;  o[5] = accA1.y * dvn + b1.y;
    o[6] = accA1.z * dvn + b1.z;  o[7] = accA1.w * dvn + b1.w;
    #pragma unroll
    for (int j = 0; j < 8; j++) o[j] = o[j] >= 0.f ? o[j] : av * o[j];

    if (F16OUT) {
        // cols [lane*4 .. lane*4+3] and [128+lane*4 ..]: two uint2 stores
        HF2 p0, p1; uint2 u;
        p0.h2 = __halves2half2(__float2half_rn(o[0]), __float2half_rn(o[1]));
        p1.h2 = __halves2half2(__float2half_rn(o[2]), __float2half_rn(o[3]));
        u.x = p0.u; u.y = p1.u;
        *(uint2*)(outh + (size_t)node * C + lane * 4) = u;
        p0.h2 = __halves2half2(__float2half_rn(o[4]), __float2half_rn(o[5]));
        p1.h2 = __halves2half2(__float2half_rn(o[6]), __float2half_rn(o[7]));
        u.x = p0.u; u.y = p1.u;
        *(uint2*)(outh + (size_t)node * C + 128 + lane * 4) = u;
    } else {
        float4* op = (float4*)(outf + (size_t)node * C);
        op[lane] = make_float4(o[0], o[1], o[2], o[3]);
        op[lane + 32] = make_float4(o[4], o[5], o[6], o[7]);
    }
}

// ---------------------------------------------------------------------------
// Launch: side stream hides conv_w + CSR under GEMM1 (R13 structure)
// ---------------------------------------------------------------------------
extern "C" void kernel_launch(void* const* d_in, const int* in_sizes, int n_in,
                              void* d_out, int out_size) {
    const float* x  = (const float*)d_in[0];
    const float* W1 = (const float*)d_in[1];
    const float* b1 = (const float*)d_in[2];
    const float* W2 = (const float*)d_in[3];
    const float* b2 = (const float*)d_in[4];
    const float* a  = (const float*)d_in[5];
    const int* eidx = (const int*)d_in[6];

    const int M = in_sizes[0] / C;     // 50000
    const int E = in_sizes[6] / 2;     // 800000
    const int* src = eidx;
    const int* dst = eidx + E;

    float *tbuf, *dinv;
    __half *hbuf;
    int *deg, *rowptr, *cursor, *csrc;
    __half *w1hi, *w2hi;
    cudaGetSymbolAddress((void**)&tbuf, g_t);
    cudaGetSymbolAddress((void**)&hbuf, g_h);
    cudaGetSymbolAddress((void**)&dinv, g_dinv);
    cudaGetSymbolAddress((void**)&deg, g_deg);
    cudaGetSymbolAddress((void**)&rowptr, g_rowptr);
    cudaGetSymbolAddress((void**)&cursor, g_cursor);
    cudaGetSymbolAddress((void**)&csrc, g_csrc);
    cudaGetSymbolAddress((void**)&w1hi, g_w1hi);
    cudaGetSymbolAddress((void**)&w2hi, g_w2hi);
    float* outp = (float*)d_out;

    static cudaStream_t s_side = nullptr;
    static cudaEvent_t ev_fork = nullptr, ev_w = nullptr, ev_join = nullptr;
    if (!s_side) {
        cudaStreamCreateWithFlags(&s_side, cudaStreamNonBlocking);
        cudaEventCreateWithFlags(&ev_fork, cudaEventDisableTiming);
        cudaEventCreateWithFlags(&ev_w, cudaEventDisableTiming);
        cudaEventCreateWithFlags(&ev_join, cudaEventDisableTiming);
    }

    // --- fork: conv_w + CSR build on side stream ---
    cudaEventRecord(ev_fork, 0);
    cudaStreamWaitEvent(s_side, ev_fork, 0);
    conv_w<<<(C * (C / 4) + 255) / 256, 256, 0, s_side>>>(W1, w1hi);
    conv_w<<<(C * (C / 4) + 255) / 256, 256, 0, s_side>>>(W2, w2hi);
    cudaEventRecord(ev_w, s_side);
    deg_init  <<<(M + 255) / 256, 256, 0, s_side>>>(deg, M);
    deg_accum <<<(E + 255) / 256, 256, 0, s_side>>>(dst, deg, E);
    scan_build<<<1, 1024, 0, s_side>>>(deg, rowptr, cursor, dinv, M);
    csr_fill  <<<(E + 255) / 256, 256, 0, s_side>>>(src, dst, cursor, csrc, E);
    cudaEventRecord(ev_join, s_side);

    dim3 gfull((M + 127) / 128, 2);
    const int gblocks = (M + 7) / 8;

    // --- main: GEMM1 on raw fp32 x (in-staging split) ---
    cudaStreamWaitEvent(0, ev_w, 0);
    mma_gemm<<<gfull, 256>>>(x, w1hi, tbuf, M);

    // join: gathers need dinv + CSR
    cudaStreamWaitEvent(0, ev_join, 0);
    gather_nodes<1><<<gblocks, 256>>>(tbuf, nullptr, hbuf, rowptr, csrc, dinv, b1, a, M);

    // --- layer 2: single-term fp16 GEMM (h is exactly fp16 -> lo == 0) ---
    mma_gemm_f16<<<gfull, 256>>>(hbuf, w2hi, tbuf, M);
    gather_nodes<0><<<gblocks, 256>>>(tbuf, outp, nullptr, rowptr, csrc, dinv, b2, a, M);
}

// round 15
// speedup vs baseline: 1.3057x; 1.0418x over previous
#include <cuda_runtime.h>
#include <cuda_fp16.h>
#include <cstdint>

#define NN   50000
#define EE   800000
#define C    256

// ---------------------------------------------------------------------------
// Scratch (__device__ globals, allocation-free rule)
// ---------------------------------------------------------------------------
__device__ __align__(16) float  g_t[(size_t)NN * C];   // GEMM1 out (raw H, fp32)
__device__ __align__(16) __half g_h[(size_t)NN * C];   // layer-1 activations (fp16)
__device__ __align__(16) __half g_g[(size_t)NN * C];   // aggregated h (fp16)
__device__ __align__(16) __half g_w1hi[C * C];         // B^T layout [N][K]
__device__ __align__(16) __half g_w2hi[C * C];
__device__ float g_dinv[NN];
__device__ int   g_deg[NN];
__device__ int   g_rowptr[NN + 1];
__device__ int   g_cursor[NN];
__device__ int   g_csrc[EE];

__device__ __forceinline__ uint32_t smem_u32(const void* p) {
    uint32_t a;
    asm("{ .reg .u64 t; cvta.to.shared.u64 t, %1; cvt.u32.u64 %0, t; }"
        : "=r"(a) : "l"(p));
    return a;
}

// ---------------------------------------------------------------------------
// Degree / CSR build
// ---------------------------------------------------------------------------
__global__ void deg_init(int* deg, int n) {
    int i = blockIdx.x * blockDim.x + threadIdx.x;
    if (i < n) deg[i] = 0;
}
__global__ void deg_accum(const int* __restrict__ dst, int* deg, int e) {
    int i = blockIdx.x * blockDim.x + threadIdx.x;
    if (i < e) atomicAdd(&deg[dst[i]], 1);
}
__global__ void scan_build(const int* __restrict__ deg, int* __restrict__ row_ptr,
                           int* __restrict__ cursor, float* __restrict__ dinv, int n) {
    __shared__ int part[1024];
    const int T = 1024;
    int tid = threadIdx.x;
    int chunk = (n + T - 1) / T;
    int beg = tid * chunk;
    int end = min(beg + chunk, n);
    int s = 0;
    for (int i = beg; i < end; i++) s += deg[i];
    part[tid] = s;
    __syncthreads();
    for (int off = 1; off < T; off <<= 1) {
        int v = part[tid];
        int u = (tid >= off) ? part[tid - off] : 0;
        __syncthreads();
        part[tid] = v + u;
        __syncthreads();
    }
    int run = (tid > 0) ? part[tid - 1] : 0;
    for (int i = beg; i < end; i++) {
        int c = deg[i];
        row_ptr[i] = run;
        cursor[i] = run;
        dinv[i] = rsqrtf((float)(c + 1));
        run += c;
    }
    if (tid == T - 1) row_ptr[n] = part[T - 1];
}
__global__ void csr_fill(const int* __restrict__ src, const int* __restrict__ dst,
                         int* cursor, int* __restrict__ csrc, int e) {
    int i = blockIdx.x * blockDim.x + threadIdx.x;
    if (i < e) {
        int p = atomicAdd(&cursor[dst[i]], 1);
        csrc[p] = src[i];
    }
}

// ---------------------------------------------------------------------------
// W [K,N] fp32 -> B^T [N][K] fp16
// ---------------------------------------------------------------------------
union HF2 { __half2 h2; uint32_t u; };

__global__ void conv_w(const float* __restrict__ W, __half* __restrict__ hi) {
    int i = blockIdx.x * blockDim.x + threadIdx.x;      // over 256*64
    if (i >= C * (C / 4)) return;
    int n = i >> 6;
    int k4 = (i & 63) * 4;
    __half hs[4];
    #pragma unroll
    for (int j = 0; j < 4; j++)
        hs[j] = __float2half_rn(__ldg(&W[(size_t)(k4 + j) * C + n]));
    HF2 a, b; uint2 o;
    a.h2 = __halves2half2(hs[0], hs[1]); b.h2 = __halves2half2(hs[2], hs[3]);
    o.x = a.u; o.y = b.u;
    ((uint2*)hi)[i] = o;
}

// ---------------------------------------------------------------------------
// Shared MMA helpers
// ---------------------------------------------------------------------------
#define LDS_PAD 40            // fp16 elems per smem row (conflict-free ldsm)

__device__ __forceinline__ void ldsm4(uint32_t* r, uint32_t addr) {
    asm volatile("ldmatrix.sync.aligned.m8n8.x4.shared.b16 {%0,%1,%2,%3}, [%4];"
                 : "=r"(r[0]), "=r"(r[1]), "=r"(r[2]), "=r"(r[3]) : "r"(addr));
}
__device__ __forceinline__ void mma16816(float* c, const uint32_t* a, const uint32_t* b) {
    asm volatile("mma.sync.aligned.m16n8k16.row.col.f32.f16.f16.f32 "
                 "{%0,%1,%2,%3}, {%4,%5,%6,%7}, {%8,%9}, {%0,%1,%2,%3};"
                 : "+f"(c[0]), "+f"(c[1]), "+f"(c[2]), "+f"(c[3])
                 : "r"(a[0]), "r"(a[1]), "r"(a[2]), "r"(a[3]), "r"(b[0]), "r"(b[1]));
}

// ---------------------------------------------------------------------------
// GEMM1: fp32 A, in-staging fp16 split, 2-term (R13-proven):
//   H = f16(A)*Bh + f16(A - f16(A))*Bh   (fp32 out)
// ---------------------------------------------------------------------------
__global__ __launch_bounds__(256)
void mma_gemm(const float* __restrict__ A, const __half* __restrict__ Bh,
              float* __restrict__ Hs, int Mrows) {
    __shared__ __half sAh[128][LDS_PAD];
    __shared__ __half sAl[128][LDS_PAD];
    __shared__ __half sBh[128][LDS_PAD];

    int tid = threadIdx.x, lane = tid & 31, wid = tid >> 5;
    int r0 = blockIdx.x * 128;
    int n0c = blockIdx.y * 128;
    int wm = (wid & 3) * 32;
    int wn = (wid >> 2) * 64;

    int aRow = lane & 15;
    int aCol = (lane >> 4) * 8;
    int bRow = (lane & 7) + ((lane >> 4) == 1 ? 8 : 0);
    int bCol = ((lane >> 3) & 1) * 8;

    uint32_t sbAh = smem_u32(sAh), sbAl = smem_u32(sAl);
    uint32_t sbBh = smem_u32(sBh);

    float acc[2][8][4] = {};

    #pragma unroll 1
    for (int kc = 0; kc < 8; kc++) {
        int k0 = kc * 32;
        #pragma unroll
        for (int t = 0; t < 4; t++) {
            int idx = tid + t * 256;
            int row = idx >> 3;
            int c4 = (idx & 7) * 4;
            int gr = r0 + row;
            float4 v = (gr < Mrows)
                ? *(const float4*)(A + (size_t)gr * C + k0 + c4)
                : make_float4(0.f, 0.f, 0.f, 0.f);
            __half h0 = __float2half_rn(v.x), h1 = __float2half_rn(v.y);
            __half h2 = __float2half_rn(v.z), h3 = __float2half_rn(v.w);
            __half l0 = __float2half_rn(v.x - __half2float(h0));
            __half l1 = __float2half_rn(v.y - __half2float(h1));
            __half l2 = __float2half_rn(v.z - __half2float(h2));
            __half l3 = __float2half_rn(v.w - __half2float(h3));
            HF2 p0, p1; uint2 u;
            p0.h2 = __halves2half2(h0, h1); p1.h2 = __halves2half2(h2, h3);
            u.x = p0.u; u.y = p1.u;
            *(uint2*)&sAh[row][c4] = u;
            p0.h2 = __halves2half2(l0, l1); p1.h2 = __halves2half2(l2, l3);
            u.x = p0.u; u.y = p1.u;
            *(uint2*)&sAl[row][c4] = u;
        }
        #pragma unroll
        for (int t = 0; t < 2; t++) {
            int idx = tid + t * 256;
            int row = idx >> 2;
            int c8 = (idx & 3) * 8;
            *(uint4*)&sBh[row][c8] =
                *(const uint4*)(Bh + (size_t)(n0c + row) * C + k0 + c8);
        }
        __syncthreads();

        #pragma unroll
        for (int ks = 0; ks < 32; ks += 16) {
            uint32_t ah[2][4], al[2][4];
            #pragma unroll
            for (int mt = 0; mt < 2; mt++) {
                uint32_t off = (uint32_t)((wm + mt * 16 + aRow) * LDS_PAD + ks + aCol) * 2;
                ldsm4(ah[mt], sbAh + off);
                ldsm4(al[mt], sbAl + off);
            }
            #pragma unroll
            for (int nq = 0; nq < 4; nq++) {
                uint32_t bh[4];
                uint32_t off = (uint32_t)((wn + nq * 16 + bRow) * LDS_PAD + ks + bCol) * 2;
                ldsm4(bh, sbBh + off);
                #pragma unroll
                for (int sub = 0; sub < 2; sub++) {
                    int nt = nq * 2 + sub;
                    #pragma unroll
                    for (int mt = 0; mt < 2; mt++) {
                        mma16816(acc[mt][nt], ah[mt], &bh[sub * 2]);
                        mma16816(acc[mt][nt], al[mt], &bh[sub * 2]);
                    }
                }
            }
        }
        __syncthreads();
    }

    int g = lane >> 2;
    int cq = (lane & 3) * 2;
    #pragma unroll
    for (int mt = 0; mt < 2; mt++) {
        int row0 = r0 + wm + mt * 16 + g;
        int row1 = row0 + 8;
        #pragma unroll
        for (int nt = 0; nt < 8; nt++) {
            int col = n0c + wn + nt * 8 + cq;
            if (row0 < Mrows) {
                float2 v = make_float2(acc[mt][nt][0], acc[mt][nt][1]);
                *(float2*)(Hs + (size_t)row0 * C + col) = v;
            }
            if (row1 < Mrows) {
                float2 v = make_float2(acc[mt][nt][2], acc[mt][nt][3]);
                *(float2*)(Hs + (size_t)row1 * C + col) = v;
            }
        }
    }
}

// ---------------------------------------------------------------------------
// GEMM2: fp16 A (aggregated g), single-term, fused bias+PReLU epilogue:
//   out = prelu(A*Bh + b, a)   (fp32 out)
// ---------------------------------------------------------------------------
__global__ __launch_bounds__(256)
void mma_gemm_f16_epi(const __half* __restrict__ A, const __half* __restrict__ Bh,
                      const float* __restrict__ bias, const float* __restrict__ a_ptr,
                      float* __restrict__ Out, int Mrows) {
    __shared__ __half sAh[128][LDS_PAD];
    __shared__ __half sBh[128][LDS_PAD];

    int tid = threadIdx.x, lane = tid & 31, wid = tid >> 5;
    int r0 = blockIdx.x * 128;
    int n0c = blockIdx.y * 128;
    int wm = (wid & 3) * 32;
    int wn = (wid >> 2) * 64;

    int aRow = lane & 15;
    int aCol = (lane >> 4) * 8;
    int bRow = (lane & 7) + ((lane >> 4) == 1 ? 8 : 0);
    int bCol = ((lane >> 3) & 1) * 8;

    uint32_t sbAh = smem_u32(sAh);
    uint32_t sbBh = smem_u32(sBh);

    float acc[2][8][4] = {};

    #pragma unroll 1
    for (int kc = 0; kc < 8; kc++) {
        int k0 = kc * 32;
        #pragma unroll
        for (int t = 0; t < 2; t++) {
            int idx = tid + t * 256;
            int row = idx >> 2;
            int c8 = (idx & 3) * 8;
            int gr = r0 + row;
            uint4 v = (gr < Mrows)
                ? *(const uint4*)(A + (size_t)gr * C + k0 + c8)
                : make_uint4(0u, 0u, 0u, 0u);
            *(uint4*)&sAh[row][c8] = v;
        }
        #pragma unroll
        for (int t = 0; t < 2; t++) {
            int idx = tid + t * 256;
            int row = idx >> 2;
            int c8 = (idx & 3) * 8;
            *(uint4*)&sBh[row][c8] =
                *(const uint4*)(Bh + (size_t)(n0c + row) * C + k0 + c8);
        }
        __syncthreads();

        #pragma unroll
        for (int ks = 0; ks < 32; ks += 16) {
            uint32_t ah[2][4];
            #pragma unroll
            for (int mt = 0; mt < 2; mt++) {
                uint32_t off = (uint32_t)((wm + mt * 16 + aRow) * LDS_PAD + ks + aCol) * 2;
                ldsm4(ah[mt], sbAh + off);
            }
            #pragma unroll
            for (int nq = 0; nq < 4; nq++) {
                uint32_t bh[4];
                uint32_t off = (uint32_t)((wn + nq * 16 + bRow) * LDS_PAD + ks + bCol) * 2;
                ldsm4(bh, sbBh + off);
                #pragma unroll
                for (int sub = 0; sub < 2; sub++) {
                    int nt = nq * 2 + sub;
                    #pragma unroll
                    for (int mt = 0; mt < 2; mt++)
                        mma16816(acc[mt][nt], ah[mt], &bh[sub * 2]);
                }
            }
        }
        __syncthreads();
    }

    float av = __ldg(a_ptr);
    int g = lane >> 2;
    int cq = (lane & 3) * 2;
    #pragma unroll
    for (int mt = 0; mt < 2; mt++) {
        int row0 = r0 + wm + mt * 16 + g;
        int row1 = row0 + 8;
        #pragma unroll
        for (int nt = 0; nt < 8; nt++) {
            int col = n0c + wn + nt * 8 + cq;
            float bv0 = __ldg(&bias[col]);
            float bv1 = __ldg(&bias[col + 1]);
            if (row0 < Mrows) {
                float v0 = acc[mt][nt][0] + bv0;
                float v1 = acc[mt][nt][1] + bv1;
                v0 = v0 >= 0.f ? v0 : av * v0;
                v1 = v1 >= 0.f ? v1 : av * v1;
                *(float2*)(Out + (size_t)row0 * C + col) = make_float2(v0, v1);
            }
            if (row1 < Mrows) {
                float v0 = acc[mt][nt][2] + bv0;
                float v1 = acc[mt][nt][3] + bv1;
                v0 = v0 >= 0.f ? v0 : av * v0;
                v1 = v1 >= 0.f ? v1 : av * v1;
                *(float2*)(Out + (size_t)row1 * C + col) = make_float2(v0, v1);
            }
        }
    }
}

// ---------------------------------------------------------------------------
// gather1 (R14-proven): fp32 H in, bias+prelu, fp16 h out
// out[d] = prelu(dinv[d]*(sum_e dinv[s_e]*H[s_e] + dinv[d]*H[d]) + b)
// ---------------------------------------------------------------------------
__global__ __launch_bounds__(256)
void gather_nodes(const float* __restrict__ Hs, __half* __restrict__ outh,
                  const int* __restrict__ rowptr, const int* __restrict__ csrc,
                  const float* __restrict__ dinv, const float* __restrict__ bias,
                  const float* __restrict__ a_ptr, int n) {
    int node = blockIdx.x * (blockDim.x >> 5) + (threadIdx.x >> 5);
    if (node >= n) return;
    int lane = threadIdx.x & 31;

    float dvn = __ldg(&dinv[node]);
    const float4* self = (const float4*)(Hs + (size_t)node * C);
    float4 s0v = __ldg(&self[lane]);
    float4 s1v = __ldg(&self[lane + 32]);
    float4 accA0 = make_float4(s0v.x * dvn, s0v.y * dvn, s0v.z * dvn, s0v.w * dvn);
    float4 accA1 = make_float4(s1v.x * dvn, s1v.y * dvn, s1v.z * dvn, s1v.w * dvn);
    float4 accB0 = make_float4(0.f, 0.f, 0.f, 0.f);
    float4 accB1 = make_float4(0.f, 0.f, 0.f, 0.f);

    int beg = __ldg(&rowptr[node]);
    int end = __ldg(&rowptr[node + 1]);
    int p = beg;

    for (; p + 4 <= end; p += 4) {
        int s0 = __ldg(&csrc[p + 0]);
        int s1 = __ldg(&csrc[p + 1]);
        int s2 = __ldg(&csrc[p + 2]);
        int s3 = __ldg(&csrc[p + 3]);
        float d0 = __ldg(&dinv[s0]);
        float d1 = __ldg(&dinv[s1]);
        float d2 = __ldg(&dinv[s2]);
        float d3 = __ldg(&dinv[s3]);
        const float4* r0 = (const float4*)(Hs + (size_t)s0 * C);
        const float4* r1 = (const float4*)(Hs + (size_t)s1 * C);
        const float4* r2 = (const float4*)(Hs + (size_t)s2 * C);
        const float4* r3 = (const float4*)(Hs + (size_t)s3 * C);
        float4 v00 = __ldg(&r0[lane]);
        float4 v01 = __ldg(&r0[lane + 32]);
        float4 v10 = __ldg(&r1[lane]);
        float4 v11 = __ldg(&r1[lane + 32]);
        float4 v20 = __ldg(&r2[lane]);
        float4 v21 = __ldg(&r2[lane + 32]);
        float4 v30 = __ldg(&r3[lane]);
        float4 v31 = __ldg(&r3[lane + 32]);
        accA0.x += v00.x * d0; accA0.y += v00.y * d0; accA0.z += v00.z * d0; accA0.w += v00.w * d0;
        accA1.x += v01.x * d0; accA1.y += v01.y * d0; accA1.z += v01.z * d0; accA1.w += v01.w * d0;
        accB0.x += v10.x * d1; accB0.y += v10.y * d1; accB0.z += v10.z * d1; accB0.w += v10.w * d1;
        accB1.x += v11.x * d1; accB1.y += v11.y * d1; accB1.z += v11.z * d1; accB1.w += v11.w * d1;
        accA0.x += v20.x * d2; accA0.y += v20.y * d2; accA0.z += v20.z * d2; accA0.w += v20.w * d2;
        accA1.x += v21.x * d2; accA1.y += v21.y * d2; accA1.z += v21.z * d2; accA1.w += v21.w * d2;
        accB0.x += v30.x * d3; accB0.y += v30.y * d3; accB0.z += v30.z * d3; accB0.w += v30.w * d3;
        accB1.x += v31.x * d3; accB1.y += v31.y * d3; accB1.z += v31.z * d3; accB1.w += v31.w * d3;
    }
    for (; p < end; p++) {
        int s = __ldg(&csrc[p]);
        float ds = __ldg(&dinv[s]);
        const float4* r = (const float4*)(Hs + (size_t)s * C);
        float4 v0 = __ldg(&r[lane]);
        float4 v1 = __ldg(&r[lane + 32]);
        accA0.x += v0.x * ds; accA0.y += v0.y * ds; accA0.z += v0.z * ds; accA0.w += v0.w * ds;
        accA1.x += v1.x * ds; accA1.y += v1.y * ds; accA1.z += v1.z * ds; accA1.w += v1.w * ds;
    }

    accA0.x += accB0.x; accA0.y += accB0.y; accA0.z += accB0.z; accA0.w += accB0.w;
    accA1.x += accB1.x; accA1.y += accB1.y; accA1.z += accB1.z; accA1.w += accB1.w;

    float av = __ldg(a_ptr);
    float4 b0 = __ldg(&((const float4*)bias)[lane]);
    float4 b1 = __ldg(&((const float4*)bias)[lane + 32]);

    float o[8];
    o[0] = accA0.x * dvn + b0.x;  o[1] = accA0.y * dvn + b0.y;
    o[2] = accA0.z * dvn + b0.z;  o[3] = accA0.w * dvn + b0.w;
    o[4] = accA1.x * dvn + b1.x;  o[5] = accA1.y * dvn + b1.y;
    o[6] = accA1.z * dvn + b1.z;  o[7] = accA1.w * dvn + b1.w;
    #pragma unroll
    for (int j = 0; j < 8; j++) o[j] = o[j] >= 0.f ? o[j] : av * o[j];

    HF2 p0, p1; uint2 u;
    p0.h2 = __halves2half2(__float2half_rn(o[0]), __float2half_rn(o[1]));
    p1.h2 = __halves2half2(__float2half_rn(o[2]), __float2half_rn(o[3]));
    u.x = p0.u; u.y = p1.u;
    *(uint2*)(outh + (size_t)node * C + lane * 4) = u;
    p0.h2 = __halves2half2(__float2half_rn(o[4]), __float2half_rn(o[5]));
    p1.h2 = __halves2half2(__float2half_rn(o[6]), __float2half_rn(o[7]));
    u.x = p0.u; u.y = p1.u;
    *(uint2*)(outh + (size_t)node * C + 128 + lane * 4) = u;
}

// ---------------------------------------------------------------------------
// gather_h: pure linear aggregation on fp16 h (no bias/prelu), fp16 out:
// g[d] = dinv[d]*(sum_e dinv[s_e]*h[s_e] + dinv[d]*h[d])
// Lane covers 8 cols (one uint4 of halfs). All loads/stores 16B coalesced.
// ---------------------------------------------------------------------------
union U4H { uint4 u; __half2 h2[4]; };

__global__ __launch_bounds__(256)
void gather_h(const __half* __restrict__ h, __half* __restrict__ gout,
              const int* __restrict__ rowptr, const int* __restrict__ csrc,
              const float* __restrict__ dinv, int n) {
    int node = blockIdx.x * (blockDim.x >> 5) + (threadIdx.x >> 5);
    if (node >= n) return;
    int lane = threadIdx.x & 31;

    float dvn = __ldg(&dinv[node]);
    float accA[8], accB[8];
    {
        U4H sv; sv.u = __ldg((const uint4*)(h + (size_t)node * C) + lane);
        #pragma unroll
        for (int q = 0; q < 4; q++) {
            float2 f = __half22float2(sv.h2[q]);
            accA[q * 2 + 0] = f.x * dvn;
            accA[q * 2 + 1] = f.y * dvn;
            accB[q * 2 + 0] = 0.f;
            accB[q * 2 + 1] = 0.f;
        }
    }

    int beg = __ldg(&rowptr[node]);
    int end = __ldg(&rowptr[node + 1]);
    int p = beg;

    for (; p + 4 <= end; p += 4) {
        int s0 = __ldg(&csrc[p + 0]);
        int s1 = __ldg(&csrc[p + 1]);
        int s2 = __ldg(&csrc[p + 2]);
        int s3 = __ldg(&csrc[p + 3]);
        float d0 = __ldg(&dinv[s0]);
        float d1 = __ldg(&dinv[s1]);
        float d2 = __ldg(&dinv[s2]);
        float d3 = __ldg(&dinv[s3]);
        U4H v0, v1, v2, v3;
        v0.u = __ldg((const uint4*)(h + (size_t)s0 * C) + lane);
        v1.u = __ldg((const uint4*)(h + (size_t)s1 * C) + lane);
        v2.u = __ldg((const uint4*)(h + (size_t)s2 * C) + lane);
        v3.u = __ldg((const uint4*)(h + (size_t)s3 * C) + lane);
        #pragma unroll
        for (int q = 0; q < 4; q++) {
            float2 f0 = __half22float2(v0.h2[q]);
            float2 f1 = __half22float2(v1.h2[q]);
            float2 f2 = __half22float2(v2.h2[q]);
            float2 f3 = __half22float2(v3.h2[q]);
            accA[q * 2 + 0] += f0.x * d0 + f2.x * d2;
            accA[q * 2 + 1] += f0.y * d0 + f2.y * d2;
            accB[q * 2 + 0] += f1.x * d1 + f3.x * d3;
            accB[q * 2 + 1] += f1.y * d1 + f3.y * d3;
        }
    }
    for (; p < end; p++) {
        int s = __ldg(&csrc[p]);
        float ds = __ldg(&dinv[s]);
        U4H v; v.u = __ldg((const uint4*)(h + (size_t)s * C) + lane);
        #pragma unroll
        for (int q = 0; q < 4; q++) {
            float2 f = __half22float2(v.h2[q]);
            accA[q * 2 + 0] += f.x * ds;
            accA[q * 2 + 1] += f.y * ds;
        }
    }

    U4H o;
    #pragma unroll
    for (int q = 0; q < 4; q++) {
        float v0 = (accA[q * 2 + 0] + accB[q * 2 + 0]) * dvn;
        float v1 = (accA[q * 2 + 1] + accB[q * 2 + 1]) * dvn;
        o.h2[q] = __halves2half2(__float2half_rn(v0), __float2half_rn(v1));
    }
    ((uint4*)(gout + (size_t)node * C))[lane] = o.u;
}

// ---------------------------------------------------------------------------
// Launch
// ---------------------------------------------------------------------------
extern "C" void kernel_launch(void* const* d_in, const int* in_sizes, int n_in,
                              void* d_out, int out_size) {
    const float* x  = (const float*)d_in[0];
    const float* W1 = (const float*)d_in[1];
    const float* b1 = (const float*)d_in[2];
    const float* W2 = (const float*)d_in[3];
    const float* b2 = (const float*)d_in[4];
    const float* a  = (const float*)d_in[5];
    const int* eidx = (const int*)d_in[6];

    const int M = in_sizes[0] / C;     // 50000
    const int E = in_sizes[6] / 2;     // 800000
    const int* src = eidx;
    const int* dst = eidx + E;

    float *tbuf, *dinv;
    __half *hbuf, *gbuf;
    int *deg, *rowptr, *cursor, *csrc;
    __half *w1hi, *w2hi;
    cudaGetSymbolAddress((void**)&tbuf, g_t);
    cudaGetSymbolAddress((void**)&hbuf, g_h);
    cudaGetSymbolAddress((void**)&gbuf, g_g);
    cudaGetSymbolAddress((void**)&dinv, g_dinv);
    cudaGetSymbolAddress((void**)&deg, g_deg);
    cudaGetSymbolAddress((void**)&rowptr, g_rowptr);
    cudaGetSymbolAddress((void**)&cursor, g_cursor);
    cudaGetSymbolAddress((void**)&csrc, g_csrc);
    cudaGetSymbolAddress((void**)&w1hi, g_w1hi);
    cudaGetSymbolAddress((void**)&w2hi, g_w2hi);
    float* outp = (float*)d_out;

    static cudaStream_t s_side = nullptr;
    static cudaEvent_t ev_fork = nullptr, ev_w = nullptr, ev_join = nullptr;
    if (!s_side) {
        cudaStreamCreateWithFlags(&s_side, cudaStreamNonBlocking);
        cudaEventCreateWithFlags(&ev_fork, cudaEventDisableTiming);
        cudaEventCreateWithFlags(&ev_w, cudaEventDisableTiming);
        cudaEventCreateWithFlags(&ev_join, cudaEventDisableTiming);
    }

    // --- fork: conv_w + CSR build on side stream ---
    cudaEventRecord(ev_fork, 0);
    cudaStreamWaitEvent(s_side, ev_fork, 0);
    conv_w<<<(C * (C / 4) + 255) / 256, 256, 0, s_side>>>(W1, w1hi);
    conv_w<<<(C * (C / 4) + 255) / 256, 256, 0, s_side>>>(W2, w2hi);
    cudaEventRecord(ev_w, s_side);
    deg_init  <<<(M + 255) / 256, 256, 0, s_side>>>(deg, M);
    deg_accum <<<(E + 255) / 256, 256, 0, s_side>>>(dst, deg, E);
    scan_build<<<1, 1024, 0, s_side>>>(deg, rowptr, cursor, dinv, M);
    csr_fill  <<<(E + 255) / 256, 256, 0, s_side>>>(src, dst, cursor, csrc, E);
    cudaEventRecord(ev_join, s_side);

    dim3 gfull((M + 127) / 128, 2);
    const int gblocks = (M + 7) / 8;

    // --- layer 1: GEMM1 (fp32 x, 2-term) -> gather1 (bias+prelu, fp16 h) ---
    cudaStreamWaitEvent(0, ev_w, 0);
    mma_gemm<<<gfull, 256>>>(x, w1hi, tbuf, M);

    cudaStreamWaitEvent(0, ev_join, 0);
    gather_nodes<<<gblocks, 256>>>(tbuf, hbuf, rowptr, csrc, dinv, b1, a, M);

    // --- layer 2 (commuted): aggregate fp16 h -> g, then GEMM + fused epi ---
    gather_h<<<gblocks, 256>>>(hbuf, gbuf, rowptr, csrc, dinv, M);
    mma_gemm_f16_epi<<<gfull, 256>>>(gbuf, w2hi, b2, a, outp, M);
}

// round 16
// speedup vs baseline: 1.3697x; 1.0490x over previous
#include <cuda_runtime.h>
#include <cuda_fp16.h>
#include <cstdint>

#define NN   50000
#define EE   800000
#define C    256

// ---------------------------------------------------------------------------
// Scratch (__device__ globals, allocation-free rule)
// ---------------------------------------------------------------------------
__device__ __align__(16) __half g_H[(size_t)NN * C];   // GEMM1 out (fp16 H)
__device__ __align__(16) __half g_h[(size_t)NN * C];   // layer-1 activations (fp16)
__device__ __align__(16) __half g_g[(size_t)NN * C];   // aggregated h (fp16)
__device__ __align__(16) __half g_w1hi[C * C];         // B^T layout [N][K]
__device__ __align__(16) __half g_w2hi[C * C];
__device__ float g_dinv[NN];
__device__ int   g_deg[NN];
__device__ int   g_rowptr[NN + 1];
__device__ int   g_cursor[NN];
__device__ int   g_csrc[EE];

__device__ __forceinline__ uint32_t smem_u32(const void* p) {
    uint32_t a;
    asm("{ .reg .u64 t; cvta.to.shared.u64 t, %1; cvt.u32.u64 %0, t; }"
        : "=r"(a) : "l"(p));
    return a;
}

// ---------------------------------------------------------------------------
// Degree / CSR build
// ---------------------------------------------------------------------------
__global__ void deg_init(int* deg, int n) {
    int i = blockIdx.x * blockDim.x + threadIdx.x;
    if (i < n) deg[i] = 0;
}
__global__ void deg_accum(const int* __restrict__ dst, int* deg, int e) {
    int i = blockIdx.x * blockDim.x + threadIdx.x;
    if (i < e) atomicAdd(&deg[dst[i]], 1);
}
__global__ void scan_build(const int* __restrict__ deg, int* __restrict__ row_ptr,
                           int* __restrict__ cursor, float* __restrict__ dinv, int n) {
    __shared__ int part[1024];
    const int T = 1024;
    int tid = threadIdx.x;
    int chunk = (n + T - 1) / T;
    int beg = tid * chunk;
    int end = min(beg + chunk, n);
    int s = 0;
    for (int i = beg; i < end; i++) s += deg[i];
    part[tid] = s;
    __syncthreads();
    for (int off = 1; off < T; off <<= 1) {
        int v = part[tid];
        int u = (tid >= off) ? part[tid - off] : 0;
        __syncthreads();
        part[tid] = v + u;
        __syncthreads();
    }
    int run = (tid > 0) ? part[tid - 1] : 0;
    for (int i = beg; i < end; i++) {
        int c = deg[i];
        row_ptr[i] = run;
        cursor[i] = run;
        dinv[i] = rsqrtf((float)(c + 1));
        run += c;
    }
    if (tid == T - 1) row_ptr[n] = part[T - 1];
}
__global__ void csr_fill(const int* __restrict__ src, const int* __restrict__ dst,
                         int* cursor, int* __restrict__ csrc, int e) {
    int i = blockIdx.x * blockDim.x + threadIdx.x;
    if (i < e) {
        int p = atomicAdd(&cursor[dst[i]], 1);
        csrc[p] = src[i];
    }
}

// ---------------------------------------------------------------------------
// W [K,N] fp32 -> B^T [N][K] fp16
// ---------------------------------------------------------------------------
union HF2 { __half2 h2; uint32_t u; };

__global__ void conv_w(const float* __restrict__ W, __half* __restrict__ hi) {
    int i = blockIdx.x * blockDim.x + threadIdx.x;      // over 256*64
    if (i >= C * (C / 4)) return;
    int n = i >> 6;
    int k4 = (i & 63) * 4;
    __half hs[4];
    #pragma unroll
    for (int j = 0; j < 4; j++)
        hs[j] = __float2half_rn(__ldg(&W[(size_t)(k4 + j) * C + n]));
    HF2 a, b; uint2 o;
    a.h2 = __halves2half2(hs[0], hs[1]); b.h2 = __halves2half2(hs[2], hs[3]);
    o.x = a.u; o.y = b.u;
    ((uint2*)hi)[i] = o;
}

// ---------------------------------------------------------------------------
// Shared MMA helpers
// ---------------------------------------------------------------------------
#define LDS_PAD 40            // fp16 elems per smem row (conflict-free ldsm)

__device__ __forceinline__ void ldsm4(uint32_t* r, uint32_t addr) {
    asm volatile("ldmatrix.sync.aligned.m8n8.x4.shared.b16 {%0,%1,%2,%3}, [%4];"
                 : "=r"(r[0]), "=r"(r[1]), "=r"(r[2]), "=r"(r[3]) : "r"(addr));
}
__device__ __forceinline__ void mma16816(float* c, const uint32_t* a, const uint32_t* b) {
    asm volatile("mma.sync.aligned.m16n8k16.row.col.f32.f16.f16.f32 "
                 "{%0,%1,%2,%3}, {%4,%5,%6,%7}, {%8,%9}, {%0,%1,%2,%3};"
                 : "+f"(c[0]), "+f"(c[1]), "+f"(c[2]), "+f"(c[3])
                 : "r"(a[0]), "r"(a[1]), "r"(a[2]), "r"(a[3]), "r"(b[0]), "r"(b[1]));
}

// ---------------------------------------------------------------------------
// GEMM1: fp32 A, in-staging fp16 split, 2-term, fp16 H out:
//   H = f16( f16(A)*Bh + f16(A - f16(A))*Bh )
// ---------------------------------------------------------------------------
__global__ __launch_bounds__(256)
void mma_gemm(const float* __restrict__ A, const __half* __restrict__ Bh,
              __half* __restrict__ Hs, int Mrows) {
    __shared__ __half sAh[128][LDS_PAD];
    __shared__ __half sAl[128][LDS_PAD];
    __shared__ __half sBh[128][LDS_PAD];

    int tid = threadIdx.x, lane = tid & 31, wid = tid >> 5;
    int r0 = blockIdx.x * 128;
    int n0c = blockIdx.y * 128;
    int wm = (wid & 3) * 32;
    int wn = (wid >> 2) * 64;

    int aRow = lane & 15;
    int aCol = (lane >> 4) * 8;
    int bRow = (lane & 7) + ((lane >> 4) == 1 ? 8 : 0);
    int bCol = ((lane >> 3) & 1) * 8;

    uint32_t sbAh = smem_u32(sAh), sbAl = smem_u32(sAl);
    uint32_t sbBh = smem_u32(sBh);

    float acc[2][8][4] = {};

    #pragma unroll 1
    for (int kc = 0; kc < 8; kc++) {
        int k0 = kc * 32;
        #pragma unroll
        for (int t = 0; t < 4; t++) {
            int idx = tid + t * 256;
            int row = idx >> 3;
            int c4 = (idx & 7) * 4;
            int gr = r0 + row;
            float4 v = (gr < Mrows)
                ? *(const float4*)(A + (size_t)gr * C + k0 + c4)
                : make_float4(0.f, 0.f, 0.f, 0.f);
            __half h0 = __float2half_rn(v.x), h1 = __float2half_rn(v.y);
            __half h2 = __float2half_rn(v.z), h3 = __float2half_rn(v.w);
            __half l0 = __float2half_rn(v.x - __half2float(h0));
            __half l1 = __float2half_rn(v.y - __half2float(h1));
            __half l2 = __float2half_rn(v.z - __half2float(h2));
            __half l3 = __float2half_rn(v.w - __half2float(h3));
            HF2 p0, p1; uint2 u;
            p0.h2 = __halves2half2(h0, h1); p1.h2 = __halves2half2(h2, h3);
            u.x = p0.u; u.y = p1.u;
            *(uint2*)&sAh[row][c4] = u;
            p0.h2 = __halves2half2(l0, l1); p1.h2 = __halves2half2(l2, l3);
            u.x = p0.u; u.y = p1.u;
            *(uint2*)&sAl[row][c4] = u;
        }
        #pragma unroll
        for (int t = 0; t < 2; t++) {
            int idx = tid + t * 256;
            int row = idx >> 2;
            int c8 = (idx & 3) * 8;
            *(uint4*)&sBh[row][c8] =
                *(const uint4*)(Bh + (size_t)(n0c + row) * C + k0 + c8);
        }
        __syncthreads();

        #pragma unroll
        for (int ks = 0; ks < 32; ks += 16) {
            uint32_t ah[2][4], al[2][4];
            #pragma unroll
            for (int mt = 0; mt < 2; mt++) {
                uint32_t off = (uint32_t)((wm + mt * 16 + aRow) * LDS_PAD + ks + aCol) * 2;
                ldsm4(ah[mt], sbAh + off);
                ldsm4(al[mt], sbAl + off);
            }
            #pragma unroll
            for (int nq = 0; nq < 4; nq++) {
                uint32_t bh[4];
                uint32_t off = (uint32_t)((wn + nq * 16 + bRow) * LDS_PAD + ks + bCol) * 2;
                ldsm4(bh, sbBh + off);
                #pragma unroll
                for (int sub = 0; sub < 2; sub++) {
                    int nt = nq * 2 + sub;
                    #pragma unroll
                    for (int mt = 0; mt < 2; mt++) {
                        mma16816(acc[mt][nt], ah[mt], &bh[sub * 2]);
                        mma16816(acc[mt][nt], al[mt], &bh[sub * 2]);
                    }
                }
            }
        }
        __syncthreads();
    }

    // Epilogue: fp16 H. Adjacent lanes cover adjacent col-pairs -> full sectors.
    int g = lane >> 2;
    int cq = (lane & 3) * 2;
    #pragma unroll
    for (int mt = 0; mt < 2; mt++) {
        int row0 = r0 + wm + mt * 16 + g;
        int row1 = row0 + 8;
        #pragma unroll
        for (int nt = 0; nt < 8; nt++) {
            int col = n0c + wn + nt * 8 + cq;
            if (row0 < Mrows) {
                *(__half2*)(Hs + (size_t)row0 * C + col) =
                    __floats2half2_rn(acc[mt][nt][0], acc[mt][nt][1]);
            }
            if (row1 < Mrows) {
                *(__half2*)(Hs + (size_t)row1 * C + col) =
                    __floats2half2_rn(acc[mt][nt][2], acc[mt][nt][3]);
            }
        }
    }
}

// ---------------------------------------------------------------------------
// GEMM2: fp16 A (aggregated g), single-term, fused bias+PReLU epilogue:
//   out = prelu(A*Bh + b, a)   (fp32 out)
// ---------------------------------------------------------------------------
__global__ __launch_bounds__(256)
void mma_gemm_f16_epi(const __half* __restrict__ A, const __half* __restrict__ Bh,
                      const float* __restrict__ bias, const float* __restrict__ a_ptr,
                      float* __restrict__ Out, int Mrows) {
    __shared__ __half sAh[128][LDS_PAD];
    __shared__ __half sBh[128][LDS_PAD];

    int tid = threadIdx.x, lane = tid & 31, wid = tid >> 5;
    int r0 = blockIdx.x * 128;
    int n0c = blockIdx.y * 128;
    int wm = (wid & 3) * 32;
    int wn = (wid >> 2) * 64;

    int aRow = lane & 15;
    int aCol = (lane >> 4) * 8;
    int bRow = (lane & 7) + ((lane >> 4) == 1 ? 8 : 0);
    int bCol = ((lane >> 3) & 1) * 8;

    uint32_t sbAh = smem_u32(sAh);
    uint32_t sbBh = smem_u32(sBh);

    float acc[2][8][4] = {};

    #pragma unroll 1
    for (int kc = 0; kc < 8; kc++) {
        int k0 = kc * 32;
        #pragma unroll
        for (int t = 0; t < 2; t++) {
            int idx = tid + t * 256;
            int row = idx >> 2;
            int c8 = (idx & 3) * 8;
            int gr = r0 + row;
            uint4 v = (gr < Mrows)
                ? *(const uint4*)(A + (size_t)gr * C + k0 + c8)
                : make_uint4(0u, 0u, 0u, 0u);
            *(uint4*)&sAh[row][c8] = v;
        }
        #pragma unroll
        for (int t = 0; t < 2; t++) {
            int idx = tid + t * 256;
            int row = idx >> 2;
            int c8 = (idx & 3) * 8;
            *(uint4*)&sBh[row][c8] =
                *(const uint4*)(Bh + (size_t)(n0c + row) * C + k0 + c8);
        }
        __syncthreads();

        #pragma unroll
        for (int ks = 0; ks < 32; ks += 16) {
            uint32_t ah[2][4];
            #pragma unroll
            for (int mt = 0; mt < 2; mt++) {
                uint32_t off = (uint32_t)((wm + mt * 16 + aRow) * LDS_PAD + ks + aCol) * 2;
                ldsm4(ah[mt], sbAh + off);
            }
            #pragma unroll
            for (int nq = 0; nq < 4; nq++) {
                uint32_t bh[4];
                uint32_t off = (uint32_t)((wn + nq * 16 + bRow) * LDS_PAD + ks + bCol) * 2;
                ldsm4(bh, sbBh + off);
                #pragma unroll
                for (int sub = 0; sub < 2; sub++) {
                    int nt = nq * 2 + sub;
                    #pragma unroll
                    for (int mt = 0; mt < 2; mt++)
                        mma16816(acc[mt][nt], ah[mt], &bh[sub * 2]);
                }
            }
        }
        __syncthreads();
    }

    float av = __ldg(a_ptr);
    int g = lane >> 2;
    int cq = (lane & 3) * 2;
    #pragma unroll
    for (int mt = 0; mt < 2; mt++) {
        int row0 = r0 + wm + mt * 16 + g;
        int row1 = row0 + 8;
        #pragma unroll
        for (int nt = 0; nt < 8; nt++) {
            int col = n0c + wn + nt * 8 + cq;
            float bv0 = __ldg(&bias[col]);
            float bv1 = __ldg(&bias[col + 1]);
            if (row0 < Mrows) {
                float v0 = acc[mt][nt][0] + bv0;
                float v1 = acc[mt][nt][1] + bv1;
                v0 = v0 >= 0.f ? v0 : av * v0;
                v1 = v1 >= 0.f ? v1 : av * v1;
                *(float2*)(Out + (size_t)row0 * C + col) = make_float2(v0, v1);
            }
            if (row1 < Mrows) {
                float v0 = acc[mt][nt][2] + bv0;
                float v1 = acc[mt][nt][3] + bv1;
                v0 = v0 >= 0.f ? v0 : av * v0;
                v1 = v1 >= 0.f ? v1 : av * v1;
                *(float2*)(Out + (size_t)row1 * C + col) = make_float2(v0, v1);
            }
        }
    }
}

// ---------------------------------------------------------------------------
// fp16 CSR aggregation core. Lane covers 8 cols (one uint4 of halfs).
// BIAS_PRELU=1: out = prelu(agg + b, a) (gather1) ; 0: out = agg (gather_h)
// ---------------------------------------------------------------------------
union U4H { uint4 u; __half2 h2[4]; };

template <int BIAS_PRELU>
__global__ __launch_bounds__(256)
void gather_f16(const __half* __restrict__ h, __half* __restrict__ gout,
                const int* __restrict__ rowptr, const int* __restrict__ csrc,
                const float* __restrict__ dinv, const float* __restrict__ bias,
                const float* __restrict__ a_ptr, int n) {
    int node = blockIdx.x * (blockDim.x >> 5) + (threadIdx.x >> 5);
    if (node >= n) return;
    int lane = threadIdx.x & 31;

    float dvn = __ldg(&dinv[node]);
    float accA[8], accB[8];
    {
        U4H sv; sv.u = __ldg((const uint4*)(h + (size_t)node * C) + lane);
        #pragma unroll
        for (int q = 0; q < 4; q++) {
            float2 f = __half22float2(sv.h2[q]);
            accA[q * 2 + 0] = f.x * dvn;
            accA[q * 2 + 1] = f.y * dvn;
            accB[q * 2 + 0] = 0.f;
            accB[q * 2 + 1] = 0.f;
        }
    }

    int beg = __ldg(&rowptr[node]);
    int end = __ldg(&rowptr[node + 1]);
    int p = beg;

    for (; p + 4 <= end; p += 4) {
        int s0 = __ldg(&csrc[p + 0]);
        int s1 = __ldg(&csrc[p + 1]);
        int s2 = __ldg(&csrc[p + 2]);
        int s3 = __ldg(&csrc[p + 3]);
        float d0 = __ldg(&dinv[s0]);
        float d1 = __ldg(&dinv[s1]);
        float d2 = __ldg(&dinv[s2]);
        float d3 = __ldg(&dinv[s3]);
        U4H v0, v1, v2, v3;
        v0.u = __ldg((const uint4*)(h + (size_t)s0 * C) + lane);
        v1.u = __ldg((const uint4*)(h + (size_t)s1 * C) + lane);
        v2.u = __ldg((const uint4*)(h + (size_t)s2 * C) + lane);
        v3.u = __ldg((const uint4*)(h + (size_t)s3 * C) + lane);
        #pragma unroll
        for (int q = 0; q < 4; q++) {
            float2 f0 = __half22float2(v0.h2[q]);
            float2 f1 = __half22float2(v1.h2[q]);
            float2 f2 = __half22float2(v2.h2[q]);
            float2 f3 = __half22float2(v3.h2[q]);
            accA[q * 2 + 0] += f0.x * d0 + f2.x * d2;
            accA[q * 2 + 1] += f0.y * d0 + f2.y * d2;
            accB[q * 2 + 0] += f1.x * d1 + f3.x * d3;
            accB[q * 2 + 1] += f1.y * d1 + f3.y * d3;
        }
    }
    for (; p < end; p++) {
        int s = __ldg(&csrc[p]);
        float ds = __ldg(&dinv[s]);
        U4H v; v.u = __ldg((const uint4*)(h + (size_t)s * C) + lane);
        #pragma unroll
        for (int q = 0; q < 4; q++) {
            float2 f = __half22float2(v.h2[q]);
            accA[q * 2 + 0] += f.x * ds;
            accA[q * 2 + 1] += f.y * ds;
        }
    }

    U4H o;
    if (BIAS_PRELU) {
        float av = __ldg(a_ptr);
        float4 b0 = __ldg(&((const float4*)bias)[lane * 2 + 0]);
        float4 b1 = __ldg(&((const float4*)bias)[lane * 2 + 1]);
        float bb[8] = {b0.x, b0.y, b0.z, b0.w, b1.x, b1.y, b1.z, b1.w};
        #pragma unroll
        for (int q = 0; q < 4; q++) {
            float v0 = (accA[q * 2 + 0] + accB[q * 2 + 0]) * dvn + bb[q * 2 + 0];
            float v1 = (accA[q * 2 + 1] + accB[q * 2 + 1]) * dvn + bb[q * 2 + 1];
            v0 = v0 >= 0.f ? v0 : av * v0;
            v1 = v1 >= 0.f ? v1 : av * v1;
            o.h2[q] = __floats2half2_rn(v0, v1);
        }
    } else {
        #pragma unroll
        for (int q = 0; q < 4; q++) {
            float v0 = (accA[q * 2 + 0] + accB[q * 2 + 0]) * dvn;
            float v1 = (accA[q * 2 + 1] + accB[q * 2 + 1]) * dvn;
            o.h2[q] = __floats2half2_rn(v0, v1);
        }
    }
    ((uint4*)(gout + (size_t)node * C))[lane] = o.u;
}

// ---------------------------------------------------------------------------
// Launch
// ---------------------------------------------------------------------------
extern "C" void kernel_launch(void* const* d_in, const int* in_sizes, int n_in,
                              void* d_out, int out_size) {
    const float* x  = (const float*)d_in[0];
    const float* W1 = (const float*)d_in[1];
    const float* b1 = (const float*)d_in[2];
    const float* W2 = (const float*)d_in[3];
    const float* b2 = (const float*)d_in[4];
    const float* a  = (const float*)d_in[5];
    const int* eidx = (const int*)d_in[6];

    const int M = in_sizes[0] / C;     // 50000
    const int E = in_sizes[6] / 2;     // 800000
    const int* src = eidx;
    const int* dst = eidx + E;

    float* dinv;
    __half *Hbuf, *hbuf, *gbuf;
    int *deg, *rowptr, *cursor, *csrc;
    __half *w1hi, *w2hi;
    cudaGetSymbolAddress((void**)&Hbuf, g_H);
    cudaGetSymbolAddress((void**)&hbuf, g_h);
    cudaGetSymbolAddress((void**)&gbuf, g_g);
    cudaGetSymbolAddress((void**)&dinv, g_dinv);
    cudaGetSymbolAddress((void**)&deg, g_deg);
    cudaGetSymbolAddress((void**)&rowptr, g_rowptr);
    cudaGetSymbolAddress((void**)&cursor, g_cursor);
    cudaGetSymbolAddress((void**)&csrc, g_csrc);
    cudaGetSymbolAddress((void**)&w1hi, g_w1hi);
    cudaGetSymbolAddress((void**)&w2hi, g_w2hi);
    float* outp = (float*)d_out;

    static cudaStream_t s_side = nullptr;
    static cudaEvent_t ev_fork = nullptr, ev_w = nullptr, ev_join = nullptr;
    if (!s_side) {
        cudaStreamCreateWithFlags(&s_side, cudaStreamNonBlocking);
        cudaEventCreateWithFlags(&ev_fork, cudaEventDisableTiming);
        cudaEventCreateWithFlags(&ev_w, cudaEventDisableTiming);
        cudaEventCreateWithFlags(&ev_join, cudaEventDisableTiming);
    }

    // --- fork: conv_w + CSR build on side stream ---
    cudaEventRecord(ev_fork, 0);
    cudaStreamWaitEvent(s_side, ev_fork, 0);
    conv_w<<<(C * (C / 4) + 255) / 256, 256, 0, s_side>>>(W1, w1hi);
    conv_w<<<(C * (C / 4) + 255) / 256, 256, 0, s_side>>>(W2, w2hi);
    cudaEventRecord(ev_w, s_side);
    deg_init  <<<(M + 255) / 256, 256, 0, s_side>>>(deg, M);
    deg_accum <<<(E + 255) / 256, 256, 0, s_side>>>(dst, deg, E);
    scan_build<<<1, 1024, 0, s_side>>>(deg, rowptr, cursor, dinv, M);
    csr_fill  <<<(E + 255) / 256, 256, 0, s_side>>>(src, dst, cursor, csrc, E);
    cudaEventRecord(ev_join, s_side);

    dim3 gfull((M + 127) / 128, 2);
    const int gblocks = (M + 7) / 8;

    // --- layer 1: GEMM1 (fp32 x, 2-term, fp16 H) -> gather1 (fp16, bias+prelu)
    cudaStreamWaitEvent(0, ev_w, 0);
    mma_gemm<<<gfull, 256>>>(x, w1hi, Hbuf, M);

    cudaStreamWaitEvent(0, ev_join, 0);
    gather_f16<1><<<gblocks, 256>>>(Hbuf, hbuf, rowptr, csrc, dinv, b1, a, M);

    // --- layer 2 (commuted): aggregate fp16 h -> g, then GEMM + fused epi ---
    gather_f16<0><<<gblocks, 256>>>(hbuf, gbuf, rowptr, csrc, dinv, nullptr, nullptr, M);
    mma_gemm_f16_epi<<<gfull, 256>>>(gbuf, w2hi, b2, a, outp, M);
}

// round 17
// speedup vs baseline: 1.3795x; 1.0072x over previous
#include <cuda_runtime.h>
#include <cuda_fp16.h>
#include <cstdint>

#define NN   50000
#define EE   800000
#define C    256

// ---------------------------------------------------------------------------
// Scratch (__device__ globals, allocation-free rule)
// ---------------------------------------------------------------------------
__device__ __align__(16) __half g_H[(size_t)NN * C];   // GEMM1 out (fp16 H)
__device__ __align__(16) __half g_h[(size_t)NN * C];   // layer-1 activations (fp16)
__device__ __align__(16) __half g_g[(size_t)NN * C];   // aggregated h (fp16)
__device__ __align__(16) __half g_w1hi[C * C];         // B^T layout [N][K]
__device__ __align__(16) __half g_w2hi[C * C];
__device__ float g_dinv[NN];
__device__ int   g_deg[NN];
__device__ int   g_rowptr[NN + 1];
__device__ int   g_cursor[NN];
__device__ int   g_csrc[EE];

__device__ __forceinline__ uint32_t smem_u32(const void* p) {
    uint32_t a;
    asm("{ .reg .u64 t; cvta.to.shared.u64 t, %1; cvt.u32.u64 %0, t; }"
        : "=r"(a) : "l"(p));
    return a;
}

// ---------------------------------------------------------------------------
// Degree / CSR build
// ---------------------------------------------------------------------------
__global__ void deg_init(int* deg, int n) {
    int i = blockIdx.x * blockDim.x + threadIdx.x;
    if (i < n) deg[i] = 0;
}
__global__ void deg_accum(const int* __restrict__ dst, int* deg, int e) {
    int i = blockIdx.x * blockDim.x + threadIdx.x;
    if (i < e) atomicAdd(&deg[dst[i]], 1);
}
__global__ void scan_build(const int* __restrict__ deg, int* __restrict__ row_ptr,
                           int* __restrict__ cursor, float* __restrict__ dinv, int n) {
    __shared__ int part[1024];
    const int T = 1024;
    int tid = threadIdx.x;
    int chunk = (n + T - 1) / T;
    int beg = tid * chunk;
    int end = min(beg + chunk, n);
    int s = 0;
    for (int i = beg; i < end; i++) s += deg[i];
    part[tid] = s;
    __syncthreads();
    for (int off = 1; off < T; off <<= 1) {
        int v = part[tid];
        int u = (tid >= off) ? part[tid - off] : 0;
        __syncthreads();
        part[tid] = v + u;
        __syncthreads();
    }
    int run = (tid > 0) ? part[tid - 1] : 0;
    for (int i = beg; i < end; i++) {
        int c = deg[i];
        row_ptr[i] = run;
        cursor[i] = run;
        dinv[i] = rsqrtf((float)(c + 1));
        run += c;
    }
    if (tid == T - 1) row_ptr[n] = part[T - 1];
}
__global__ void csr_fill(const int* __restrict__ src, const int* __restrict__ dst,
                         int* cursor, int* __restrict__ csrc, int e) {
    int i = blockIdx.x * blockDim.x + threadIdx.x;
    if (i < e) {
        int p = atomicAdd(&cursor[dst[i]], 1);
        csrc[p] = src[i];
    }
}

// ---------------------------------------------------------------------------
// W [K,N] fp32 -> B^T [N][K] fp16
// ---------------------------------------------------------------------------
union HF2 { __half2 h2; uint32_t u; };

__global__ void conv_w(const float* __restrict__ W, __half* __restrict__ hi) {
    int i = blockIdx.x * blockDim.x + threadIdx.x;      // over 256*64
    if (i >= C * (C / 4)) return;
    int n = i >> 6;
    int k4 = (i & 63) * 4;
    __half hs[4];
    #pragma unroll
    for (int j = 0; j < 4; j++)
        hs[j] = __float2half_rn(__ldg(&W[(size_t)(k4 + j) * C + n]));
    HF2 a, b; uint2 o;
    a.h2 = __halves2half2(hs[0], hs[1]); b.h2 = __halves2half2(hs[2], hs[3]);
    o.x = a.u; o.y = b.u;
    ((uint2*)hi)[i] = o;
}

// ---------------------------------------------------------------------------
// Shared MMA helpers
// ---------------------------------------------------------------------------
#define LDS_PAD 40            // fp16 elems per smem row (conflict-free ldsm)

__device__ __forceinline__ void ldsm4(uint32_t* r, uint32_t addr) {
    asm volatile("ldmatrix.sync.aligned.m8n8.x4.shared.b16 {%0,%1,%2,%3}, [%4];"
                 : "=r"(r[0]), "=r"(r[1]), "=r"(r[2]), "=r"(r[3]) : "r"(addr));
}
__device__ __forceinline__ void mma16816(float* c, const uint32_t* a, const uint32_t* b) {
    asm volatile("mma.sync.aligned.m16n8k16.row.col.f32.f16.f16.f32 "
                 "{%0,%1,%2,%3}, {%4,%5,%6,%7}, {%8,%9}, {%0,%1,%2,%3};"
                 : "+f"(c[0]), "+f"(c[1]), "+f"(c[2]), "+f"(c[3])
                 : "r"(a[0]), "r"(a[1]), "r"(a[2]), "r"(a[3]), "r"(b[0]), "r"(b[1]));
}

// ---------------------------------------------------------------------------
// GEMM1: fp32 A converted in-staging to fp16 (single-term), fp16 H out:
//   H = f16( f16(A) * Bh )
// ---------------------------------------------------------------------------
__global__ __launch_bounds__(256)
void mma_gemm1(const float* __restrict__ A, const __half* __restrict__ Bh,
               __half* __restrict__ Hs, int Mrows) {
    __shared__ __half sAh[128][LDS_PAD];
    __shared__ __half sBh[128][LDS_PAD];

    int tid = threadIdx.x, lane = tid & 31, wid = tid >> 5;
    int r0 = blockIdx.x * 128;
    int n0c = blockIdx.y * 128;
    int wm = (wid & 3) * 32;
    int wn = (wid >> 2) * 64;

    int aRow = lane & 15;
    int aCol = (lane >> 4) * 8;
    int bRow = (lane & 7) + ((lane >> 4) == 1 ? 8 : 0);
    int bCol = ((lane >> 3) & 1) * 8;

    uint32_t sbAh = smem_u32(sAh);
    uint32_t sbBh = smem_u32(sBh);

    float acc[2][8][4] = {};

    #pragma unroll 1
    for (int kc = 0; kc < 8; kc++) {
        int k0 = kc * 32;
        // stage A: fp32 load + fp16 convert (hi only)
        #pragma unroll
        for (int t = 0; t < 4; t++) {
            int idx = tid + t * 256;
            int row = idx >> 3;
            int c4 = (idx & 7) * 4;
            int gr = r0 + row;
            float4 v = (gr < Mrows)
                ? *(const float4*)(A + (size_t)gr * C + k0 + c4)
                : make_float4(0.f, 0.f, 0.f, 0.f);
            HF2 p0, p1; uint2 u;
            p0.h2 = __floats2half2_rn(v.x, v.y);
            p1.h2 = __floats2half2_rn(v.z, v.w);
            u.x = p0.u; u.y = p1.u;
            *(uint2*)&sAh[row][c4] = u;
        }
        // stage B
        #pragma unroll
        for (int t = 0; t < 2; t++) {
            int idx = tid + t * 256;
            int row = idx >> 2;
            int c8 = (idx & 3) * 8;
            *(uint4*)&sBh[row][c8] =
                *(const uint4*)(Bh + (size_t)(n0c + row) * C + k0 + c8);
        }
        __syncthreads();

        #pragma unroll
        for (int ks = 0; ks < 32; ks += 16) {
            uint32_t ah[2][4];
            #pragma unroll
            for (int mt = 0; mt < 2; mt++) {
                uint32_t off = (uint32_t)((wm + mt * 16 + aRow) * LDS_PAD + ks + aCol) * 2;
                ldsm4(ah[mt], sbAh + off);
            }
            #pragma unroll
            for (int nq = 0; nq < 4; nq++) {
                uint32_t bh[4];
                uint32_t off = (uint32_t)((wn + nq * 16 + bRow) * LDS_PAD + ks + bCol) * 2;
                ldsm4(bh, sbBh + off);
                #pragma unroll
                for (int sub = 0; sub < 2; sub++) {
                    int nt = nq * 2 + sub;
                    #pragma unroll
                    for (int mt = 0; mt < 2; mt++)
                        mma16816(acc[mt][nt], ah[mt], &bh[sub * 2]);
                }
            }
        }
        __syncthreads();
    }

    // Epilogue: fp16 H
    int g = lane >> 2;
    int cq = (lane & 3) * 2;
    #pragma unroll
    for (int mt = 0; mt < 2; mt++) {
        int row0 = r0 + wm + mt * 16 + g;
        int row1 = row0 + 8;
        #pragma unroll
        for (int nt = 0; nt < 8; nt++) {
            int col = n0c + wn + nt * 8 + cq;
            if (row0 < Mrows) {
                *(__half2*)(Hs + (size_t)row0 * C + col) =
                    __floats2half2_rn(acc[mt][nt][0], acc[mt][nt][1]);
            }
            if (row1 < Mrows) {
                *(__half2*)(Hs + (size_t)row1 * C + col) =
                    __floats2half2_rn(acc[mt][nt][2], acc[mt][nt][3]);
            }
        }
    }
}

// ---------------------------------------------------------------------------
// GEMM2: fp16 A (aggregated g), single-term, fused bias+PReLU epilogue:
//   out = prelu(A*Bh + b, a)   (fp32 out)
// ---------------------------------------------------------------------------
__global__ __launch_bounds__(256)
void mma_gemm_f16_epi(const __half* __restrict__ A, const __half* __restrict__ Bh,
                      const float* __restrict__ bias, const float* __restrict__ a_ptr,
                      float* __restrict__ Out, int Mrows) {
    __shared__ __half sAh[128][LDS_PAD];
    __shared__ __half sBh[128][LDS_PAD];

    int tid = threadIdx.x, lane = tid & 31, wid = tid >> 5;
    int r0 = blockIdx.x * 128;
    int n0c = blockIdx.y * 128;
    int wm = (wid & 3) * 32;
    int wn = (wid >> 2) * 64;

    int aRow = lane & 15;
    int aCol = (lane >> 4) * 8;
    int bRow = (lane & 7) + ((lane >> 4) == 1 ? 8 : 0);
    int bCol = ((lane >> 3) & 1) * 8;

    uint32_t sbAh = smem_u32(sAh);
    uint32_t sbBh = smem_u32(sBh);

    float acc[2][8][4] = {};

    #pragma unroll 1
    for (int kc = 0; kc < 8; kc++) {
        int k0 = kc * 32;
        #pragma unroll
        for (int t = 0; t < 2; t++) {
            int idx = tid + t * 256;
            int row = idx >> 2;
            int c8 = (idx & 3) * 8;
            int gr = r0 + row;
            uint4 v = (gr < Mrows)
                ? *(const uint4*)(A + (size_t)gr * C + k0 + c8)
                : make_uint4(0u, 0u, 0u, 0u);
            *(uint4*)&sAh[row][c8] = v;
        }
        #pragma unroll
        for (int t = 0; t < 2; t++) {
            int idx = tid + t * 256;
            int row = idx >> 2;
            int c8 = (idx & 3) * 8;
            *(uint4*)&sBh[row][c8] =
                *(const uint4*)(Bh + (size_t)(n0c + row) * C + k0 + c8);
        }
        __syncthreads();

        #pragma unroll
        for (int ks = 0; ks < 32; ks += 16) {
            uint32_t ah[2][4];
            #pragma unroll
            for (int mt = 0; mt < 2; mt++) {
                uint32_t off = (uint32_t)((wm + mt * 16 + aRow) * LDS_PAD + ks + aCol) * 2;
                ldsm4(ah[mt], sbAh + off);
            }
            #pragma unroll
            for (int nq = 0; nq < 4; nq++) {
                uint32_t bh[4];
                uint32_t off = (uint32_t)((wn + nq * 16 + bRow) * LDS_PAD + ks + bCol) * 2;
                ldsm4(bh, sbBh + off);
                #pragma unroll
                for (int sub = 0; sub < 2; sub++) {
                    int nt = nq * 2 + sub;
                    #pragma unroll
                    for (int mt = 0; mt < 2; mt++)
                        mma16816(acc[mt][nt], ah[mt], &bh[sub * 2]);
                }
            }
        }
        __syncthreads();
    }

    float av = __ldg(a_ptr);
    int g = lane >> 2;
    int cq = (lane & 3) * 2;
    #pragma unroll
    for (int mt = 0; mt < 2; mt++) {
        int row0 = r0 + wm + mt * 16 + g;
        int row1 = row0 + 8;
        #pragma unroll
        for (int nt = 0; nt < 8; nt++) {
            int col = n0c + wn + nt * 8 + cq;
            float bv0 = __ldg(&bias[col]);
            float bv1 = __ldg(&bias[col + 1]);
            if (row0 < Mrows) {
                float v0 = acc[mt][nt][0] + bv0;
                float v1 = acc[mt][nt][1] + bv1;
                v0 = v0 >= 0.f ? v0 : av * v0;
                v1 = v1 >= 0.f ? v1 : av * v1;
                *(float2*)(Out + (size_t)row0 * C + col) = make_float2(v0, v1);
            }
            if (row1 < Mrows) {
                float v0 = acc[mt][nt][2] + bv0;
                float v1 = acc[mt][nt][3] + bv1;
                v0 = v0 >= 0.f ? v0 : av * v0;
                v1 = v1 >= 0.f ? v1 : av * v1;
                *(float2*)(Out + (size_t)row1 * C + col) = make_float2(v0, v1);
            }
        }
    }
}

// ---------------------------------------------------------------------------
// fp16 CSR aggregation core. Lane covers 8 cols (one uint4 of halfs).
// BIAS_PRELU=1: out = prelu(agg + b, a) (gather1) ; 0: out = agg (gather_h)
// ---------------------------------------------------------------------------
union U4H { uint4 u; __half2 h2[4]; };

template <int BIAS_PRELU>
__global__ __launch_bounds__(256)
void gather_f16(const __half* __restrict__ h, __half* __restrict__ gout,
                const int* __restrict__ rowptr, const int* __restrict__ csrc,
                const float* __restrict__ dinv, const float* __restrict__ bias,
                const float* __restrict__ a_ptr, int n) {
    int node = blockIdx.x * (blockDim.x >> 5) + (threadIdx.x >> 5);
    if (node >= n) return;
    int lane = threadIdx.x & 31;

    float dvn = __ldg(&dinv[node]);
    float accA[8], accB[8];
    {
        U4H sv; sv.u = __ldg((const uint4*)(h + (size_t)node * C) + lane);
        #pragma unroll
        for (int q = 0; q < 4; q++) {
            float2 f = __half22float2(sv.h2[q]);
            accA[q * 2 + 0] = f.x * dvn;
            accA[q * 2 + 1] = f.y * dvn;
            accB[q * 2 + 0] = 0.f;
            accB[q * 2 + 1] = 0.f;
        }
    }

    int beg = __ldg(&rowptr[node]);
    int end = __ldg(&rowptr[node + 1]);
    int p = beg;

    for (; p + 4 <= end; p += 4) {
        int s0 = __ldg(&csrc[p + 0]);
        int s1 = __ldg(&csrc[p + 1]);
        int s2 = __ldg(&csrc[p + 2]);
        int s3 = __ldg(&csrc[p + 3]);
        float d0 = __ldg(&dinv[s0]);
        float d1 = __ldg(&dinv[s1]);
        float d2 = __ldg(&dinv[s2]);
        float d3 = __ldg(&dinv[s3]);
        U4H v0, v1, v2, v3;
        v0.u = __ldg((const uint4*)(h + (size_t)s0 * C) + lane);
        v1.u = __ldg((const uint4*)(h + (size_t)s1 * C) + lane);
        v2.u = __ldg((const uint4*)(h + (size_t)s2 * C) + lane);
        v3.u = __ldg((const uint4*)(h + (size_t)s3 * C) + lane);
        #pragma unroll
        for (int q = 0; q < 4; q++) {
            float2 f0 = __half22float2(v0.h2[q]);
            float2 f1 = __half22float2(v1.h2[q]);
            float2 f2 = __half22float2(v2.h2[q]);
            float2 f3 = __half22float2(v3.h2[q]);
            accA[q * 2 + 0] += f0.x * d0 + f2.x * d2;
            accA[q * 2 + 1] += f0.y * d0 + f2.y * d2;
            accB[q * 2 + 0] += f1.x * d1 + f3.x * d3;
            accB[q * 2 + 1] += f1.y * d1 + f3.y * d3;
        }
    }
    for (; p < end; p++) {
        int s = __ldg(&csrc[p]);
        float ds = __ldg(&dinv[s]);
        U4H v; v.u = __ldg((const uint4*)(h + (size_t)s * C) + lane);
        #pragma unroll
        for (int q = 0; q < 4; q++) {
            float2 f = __half22float2(v.h2[q]);
            accA[q * 2 + 0] += f.x * ds;
            accA[q * 2 + 1] += f.y * ds;
        }
    }

    U4H o;
    if (BIAS_PRELU) {
        float av = __ldg(a_ptr);
        float4 b0 = __ldg(&((const float4*)bias)[lane * 2 + 0]);
        float4 b1 = __ldg(&((const float4*)bias)[lane * 2 + 1]);
        float bb[8] = {b0.x, b0.y, b0.z, b0.w, b1.x, b1.y, b1.z, b1.w};
        #pragma unroll
        for (int q = 0; q < 4; q++) {
            float v0 = (accA[q * 2 + 0] + accB[q * 2 + 0]) * dvn + bb[q * 2 + 0];
            float v1 = (accA[q * 2 + 1] + accB[q * 2 + 1]) * dvn + bb[q * 2 + 1];
            v0 = v0 >= 0.f ? v0 : av * v0;
            v1 = v1 >= 0.f ? v1 : av * v1;
            o.h2[q] = __floats2half2_rn(v0, v1);
        }
    } else {
        #pragma unroll
        for (int q = 0; q < 4; q++) {
            float v0 = (accA[q * 2 + 0] + accB[q * 2 + 0]) * dvn;
            float v1 = (accA[q * 2 + 1] + accB[q * 2 + 1]) * dvn;
            o.h2[q] = __floats2half2_rn(v0, v1);
        }
    }
    ((uint4*)(gout + (size_t)node * C))[lane] = o.u;
}

// ---------------------------------------------------------------------------
// Launch
// ---------------------------------------------------------------------------
extern "C" void kernel_launch(void* const* d_in, const int* in_sizes, int n_in,
                              void* d_out, int out_size) {
    const float* x  = (const float*)d_in[0];
    const float* W1 = (const float*)d_in[1];
    const float* b1 = (const float*)d_in[2];
    const float* W2 = (const float*)d_in[3];
    const float* b2 = (const float*)d_in[4];
    const float* a  = (const float*)d_in[5];
    const int* eidx = (const int*)d_in[6];

    const int M = in_sizes[0] / C;     // 50000
    const int E = in_sizes[6] / 2;     // 800000
    const int* src = eidx;
    const int* dst = eidx + E;

    float* dinv;
    __half *Hbuf, *hbuf, *gbuf;
    int *deg, *rowptr, *cursor, *csrc;
    __half *w1hi, *w2hi;
    cudaGetSymbolAddress((void**)&Hbuf, g_H);
    cudaGetSymbolAddress((void**)&hbuf, g_h);
    cudaGetSymbolAddress((void**)&gbuf, g_g);
    cudaGetSymbolAddress((void**)&dinv, g_dinv);
    cudaGetSymbolAddress((void**)&deg, g_deg);
    cudaGetSymbolAddress((void**)&rowptr, g_rowptr);
    cudaGetSymbolAddress((void**)&cursor, g_cursor);
    cudaGetSymbolAddress((void**)&csrc, g_csrc);
    cudaGetSymbolAddress((void**)&w1hi, g_w1hi);
    cudaGetSymbolAddress((void**)&w2hi, g_w2hi);
    float* outp = (float*)d_out;

    static cudaStream_t s_side = nullptr;
    static cudaEvent_t ev_fork = nullptr, ev_w = nullptr, ev_join = nullptr;
    if (!s_side) {
        cudaStreamCreateWithFlags(&s_side, cudaStreamNonBlocking);
        cudaEventCreateWithFlags(&ev_fork, cudaEventDisableTiming);
        cudaEventCreateWithFlags(&ev_w, cudaEventDisableTiming);
        cudaEventCreateWithFlags(&ev_join, cudaEventDisableTiming);
    }

    // --- fork: conv_w + CSR build on side stream ---
    cudaEventRecord(ev_fork, 0);
    cudaStreamWaitEvent(s_side, ev_fork, 0);
    conv_w<<<(C * (C / 4) + 255) / 256, 256, 0, s_side>>>(W1, w1hi);
    conv_w<<<(C * (C / 4) + 255) / 256, 256, 0, s_side>>>(W2, w2hi);
    cudaEventRecord(ev_w, s_side);
    deg_init  <<<(M + 255) / 256, 256, 0, s_side>>>(deg, M);
    deg_accum <<<(E + 255) / 256, 256, 0, s_side>>>(dst, deg, E);
    scan_build<<<1, 1024, 0, s_side>>>(deg, rowptr, cursor, dinv, M);
    csr_fill  <<<(E + 255) / 256, 256, 0, s_side>>>(src, dst, cursor, csrc, E);
    cudaEventRecord(ev_join, s_side);

    dim3 gfull((M + 127) / 128, 2);
    const int gblocks = (M + 7) / 8;

    // --- layer 1: GEMM1 (single-term fp16) -> gather1 (fp16, bias+prelu) ---
    cudaStreamWaitEvent(0, ev_w, 0);
    mma_gemm1<<<gfull, 256>>>(x, w1hi, Hbuf, M);

    cudaStreamWaitEvent(0, ev_join, 0);
    gather_f16<1><<<gblocks, 256>>>(Hbuf, hbuf, rowptr, csrc, dinv, b1, a, M);

    // --- layer 2 (commuted): aggregate fp16 h -> g, then GEMM + fused epi ---
    gather_f16<0><<<gblocks, 256>>>(hbuf, gbuf, rowptr, csrc, dinv, nullptr, nullptr, M);
    mma_gemm_f16_epi<<<gfull, 256>>>(gbuf, w2hi, b2, a, outp, M);
}